// round 13
// baseline (speedup 1.0000x reference)
#include <cuda_runtime.h>
#include <cuda_bf16.h>
#include <cuda_fp16.h>
#include <cstddef>
#include <cstdint>

// ---------------------------------------------------------------------------
// Problem constants
// ---------------------------------------------------------------------------
#define NMAX   200000
#define EMAX   650000
#define EMB    128
#define ENC1   256
#define NEG_SLOPE 0.1f
#define LN_EPS 1e-5f

// ---------------------------------------------------------------------------
// Scratch (static __device__ arrays; no allocations allowed)
// ---------------------------------------------------------------------------
__device__ float g_H[4][(size_t)NMAX * EMB];   // h_list[0..3]
__device__ float g_AGG[(size_t)NMAX * EMB];    // pass-A aggregated output (fp32)
__device__ float g_H1[(size_t)NMAX * ENC1];    // encoder intermediate
__device__ __half2 g_YA[(size_t)NMAX * 64];    // fp16 messages, pass A
__device__ __half2 g_YB[(size_t)NMAX * 64];    // fp16 messages, pass B
__device__ __half2 g_IN[(size_t)NMAX * 64];    // fp16 init (self term), reused A/B
__device__ float g_disA[NMAX];
__device__ float g_disB[NMAX];
__device__ float g_invA[NMAX];
__device__ float g_invB[NMAX];
// CSR scratch: [0,N) rowcntA | [N,2N) rowcntB | [2N,4N) colcnt (A then B)
//              [4N,6N) cursors (A then B)
__device__ int g_icsr[6 * NMAX];
__device__ int g_offs[2 * NMAX];
__device__ int g_src[2 * EMAX];
__device__ int g_bsums[512];
// Prepped weight chunks: 18 chunks of [128 n x 64 k] bf16, XOR-swizzled, hi/lo.
__device__ __nv_bfloat16 g_Bhi[18 * 8192];
__device__ __nv_bfloat16 g_Blo[18 * 8192];

// ---------------------------------------------------------------------------
// Helpers
// ---------------------------------------------------------------------------
__device__ __forceinline__ float leaky(float v) {
    return v >= 0.0f ? v : NEG_SLOPE * v;
}
__device__ __forceinline__ float relu_(float v) { return fmaxf(v, 0.0f); }

__device__ __forceinline__ uint32_t smem_u32(const void* p) {
    uint32_t a;
    asm("{ .reg .u64 t; cvta.to.shared.u64 t, %1; cvt.u32.u64 %0, t; }"
        : "=r"(a) : "l"(p));
    return a;
}

__device__ __forceinline__ void ldsm4(uint32_t* r, uint32_t addr) {
    asm volatile("ldmatrix.sync.aligned.m8n8.x4.shared.b16 {%0,%1,%2,%3}, [%4];"
                 : "=r"(r[0]), "=r"(r[1]), "=r"(r[2]), "=r"(r[3]) : "r"(addr));
}

__device__ __forceinline__ void mma16816(float* c, const uint32_t* a,
                                         uint32_t b0, uint32_t b1) {
    asm volatile(
        "mma.sync.aligned.m16n8k16.row.col.f32.bf16.bf16.f32 "
        "{%0,%1,%2,%3}, {%4,%5,%6,%7}, {%8,%9}, {%0,%1,%2,%3};"
        : "+f"(c[0]), "+f"(c[1]), "+f"(c[2]), "+f"(c[3])
        : "r"(a[0]), "r"(a[1]), "r"(a[2]), "r"(a[3]), "r"(b0), "r"(b1));
}

// fp32x4 -> swizzled bf16 hi/lo store (packed converts)
__device__ __forceinline__ void store_hilo(char* smbase, int off, float4 v) {
    __nv_bfloat162 h01 = __float22bfloat162_rn(make_float2(v.x, v.y));
    __nv_bfloat162 h23 = __float22bfloat162_rn(make_float2(v.z, v.w));
    float2 hf01 = __bfloat1622float2(h01);
    float2 hf23 = __bfloat1622float2(h23);
    __nv_bfloat162 l01 = __float22bfloat162_rn(make_float2(v.x - hf01.x, v.y - hf01.y));
    __nv_bfloat162 l23 = __float22bfloat162_rn(make_float2(v.z - hf23.x, v.w - hf23.y));
    uint2 hi = make_uint2(*reinterpret_cast<uint32_t*>(&h01),
                          *reinterpret_cast<uint32_t*>(&h23));
    uint2 lo = make_uint2(*reinterpret_cast<uint32_t*>(&l01),
                          *reinterpret_cast<uint32_t*>(&l23));
    *(uint2*)(smbase + 0     + off) = hi;   // SM_A_HI == 0
    *(uint2*)(smbase + 16384 + off) = lo;   // SM_A_LO == 16384
}

// ---------------------------------------------------------------------------
// CSR build kernels
// ---------------------------------------------------------------------------
__global__ void zero_kernel(int* p, int n) {
    int i = blockIdx.x * blockDim.x + threadIdx.x;
    if (i < n) p[i] = 0;
}

__global__ void hist2_kernel(const int* __restrict__ rows,
                             const int* __restrict__ cols,
                             int* __restrict__ rowcnt,
                             int* __restrict__ colcnt, int E) {
    int e = blockIdx.x * blockDim.x + threadIdx.x;
    if (e >= E) return;
    atomicAdd(&rowcnt[rows[e]], 1);
    atomicAdd(&colcnt[cols[e]], 1);
}

__global__ void deg_fin_kernel(const int* __restrict__ cnt,
                               float* __restrict__ dis,
                               float* __restrict__ inv, int n) {
    int i = blockIdx.x * blockDim.x + threadIdx.x;
    if (i < n) {
        float d = (float)(cnt[i] + 1);
        dis[i] = rsqrtf(d);
        inv[i] = 1.0f / d;
    }
}

__global__ void scan_block_kernel(const int* __restrict__ in, int* __restrict__ out,
                                  int* __restrict__ bsums, int n) {
    __shared__ int sh[256];
    const int base = blockIdx.x * 1024;
    const int t = threadIdx.x;
    int v[4]; int s = 0;
#pragma unroll
    for (int j = 0; j < 4; j++) {
        int i = base + t * 4 + j;
        v[j] = (i < n) ? in[i] : 0;
        s += v[j];
    }
    sh[t] = s;
    __syncthreads();
    for (int off = 1; off < 256; off <<= 1) {
        int x = (t >= off) ? sh[t - off] : 0;
        __syncthreads();
        sh[t] += x;
        __syncthreads();
    }
    int run = (t > 0) ? sh[t - 1] : 0;
    if (t == 255) bsums[blockIdx.x] = sh[255];
#pragma unroll
    for (int j = 0; j < 4; j++) {
        int i = base + t * 4 + j;
        if (i < n) out[i] = run;
        run += v[j];
    }
}

__global__ void scan_sums_kernel(int* bsums, int nb) {
    __shared__ int sh[512];
    int t = threadIdx.x;
    sh[t] = (t < nb) ? bsums[t] : 0;
    __syncthreads();
    for (int off = 1; off < 512; off <<= 1) {
        int x = (t >= off) ? sh[t - off] : 0;
        __syncthreads();
        sh[t] += x;
        __syncthreads();
    }
    if (t < nb) bsums[t] = (t > 0) ? sh[t - 1] : 0;
}

__global__ void scan_add_kernel(int* __restrict__ out, const int* __restrict__ bsums,
                                int n) {
    int i = blockIdx.x * blockDim.x + threadIdx.x;
    if (i < n) out[i] += bsums[i >> 10];
}

__global__ void fill_kernel(const int* __restrict__ rows, const int* __restrict__ cols,
                            const int* __restrict__ offs, int* __restrict__ cursor,
                            int* __restrict__ src, int E, int obase) {
    int e = blockIdx.x * blockDim.x + threadIdx.x;
    if (e >= E) return;
    int c = cols[e];
    int pos = offs[obase + c] + atomicAdd(&cursor[obase + c], 1);
    src[pos] = rows[e];
}

// ---------------------------------------------------------------------------
// Merged weight prep: 18 chunks of [128n x 64k], swizzled bf16 hi/lo
// ---------------------------------------------------------------------------
__global__ void prep_all_kernel(const float* __restrict__ enc_w1,
                                const float* __restrict__ enc_w2,
                                const float* __restrict__ conv_w,
                                const float* __restrict__ reconv_w,
                                __nv_bfloat16* __restrict__ BH,
                                __nv_bfloat16* __restrict__ BL) {
    const int chunk = blockIdx.x >> 5;
    const int idx = (blockIdx.x & 31) * 256 + threadIdx.x;
    const int n = idx >> 6;
    const int k = idx & 63;
    const float* W; int ldn, k0, n0, kcount;
    if (chunk < 2)      { W = enc_w1; ldn = 256; k0 = 0; n0 = chunk * 128; kcount = 32; }
    else if (chunk < 6) { W = enc_w2; ldn = 128; k0 = (chunk - 2) * 64; n0 = 0; kcount = 64; }
    else if (chunk < 12) {
        int l = (chunk - 6) >> 1, c = (chunk - 6) & 1;
        W = conv_w + (size_t)l * 16384; ldn = 128; k0 = c * 64; n0 = 0; kcount = 64;
    } else {
        int l = (chunk - 12) >> 1, c = (chunk - 12) & 1;
        W = reconv_w + (size_t)l * 16384; ldn = 128; k0 = c * 64; n0 = 0; kcount = 64;
    }
    float v = (k < kcount) ? W[(size_t)(k0 + k) * ldn + n0 + n] : 0.0f;
    __nv_bfloat16 h = __float2bfloat16(v);
    __nv_bfloat16 l = __float2bfloat16(v - __bfloat162float(h));
    int off = n * 128 + ((k * 2) ^ ((n & 7) << 4));
    BH[(size_t)chunk * 8192 + (off >> 1)] = h;
    BL[(size_t)chunk * 8192 + (off >> 1)] = l;
}

// ---------------------------------------------------------------------------
// Tensor-core GEMM (mma.sync bf16 3-split): d = A[M,KV] @ W + bias
//  mode 0: out[gr*ostride+colofs+n] = act? leaky(d) : d
//          if (aux && gr<rows_aux) also aux[gr*512+aofs+n]
//  mode 1 (GCN prep): ibuf[gr][n] = half( relu(d+root[n]) * inv[gr] )  (init)
//                     ybuf[gr][n] = half( dis[gr] * relu(d) )          (message)
// ---------------------------------------------------------------------------
#define SM_A_HI 0
#define SM_A_LO 16384
#define SM_B_HI 32768
#define SM_B_LO 49152
#define SMEM_TC 65536

__global__ void __launch_bounds__(256, 2)
gemm_tc_kernel(const float* __restrict__ A, int lda, int M,
               const __nv_bfloat16* __restrict__ BhiG,
               const __nv_bfloat16* __restrict__ BloG,
               int kchunks, int KV,
               const float* __restrict__ bias,
               float* __restrict__ out, int ostride, int colofs, int act,
               float* __restrict__ aux, int aofs, int rows_aux,
               int mode,
               const float* __restrict__ root,
               const float* __restrict__ dis,
               const float* __restrict__ inv,
               __half2* __restrict__ ybuf,
               __half2* __restrict__ ibuf) {
    extern __shared__ char sm[];
    const uint32_t sb = smem_u32(sm);
    const int tid = threadIdx.x;
    const int w = tid >> 5;
    const int lane = tid & 31;
    const int wm = w & 3;
    const int wn = w >> 2;
    const int row0 = blockIdx.x * 128;

    float acc[2][8][4];
#pragma unroll
    for (int a = 0; a < 2; a++)
#pragma unroll
        for (int b = 0; b < 8; b++)
#pragma unroll
            for (int c = 0; c < 4; c++) acc[a][b][c] = 0.0f;

    for (int ck = 0; ck < kchunks; ck++) {
        const int kbase = ck * 64;
        int kcols = KV - kbase; if (kcols > 64) kcols = 64;
        const int ksteps = (kcols + 15) >> 4;

        // ---- stage B chunk ----
        {
            const float4* shg = (const float4*)(BhiG + (size_t)ck * 8192);
            const float4* slg = (const float4*)(BloG + (size_t)ck * 8192);
            float4* dh = (float4*)(sm + SM_B_HI);
            float4* dl = (float4*)(sm + SM_B_LO);
            for (int i = tid; i < 1024; i += 256) { dh[i] = shg[i]; dl[i] = slg[i]; }
        }

        // ---- stage A chunk [128 x 64] fp32 -> bf16 hi/lo, swizzled ----
#pragma unroll
        for (int i = 0; i < 8; i++) {
            const int idx = tid + i * 256;
            const int r = idx >> 4;
            const int c4 = idx & 15;
            float4 v = make_float4(0.f, 0.f, 0.f, 0.f);
            const int gr = row0 + r;
            if (gr < M && c4 * 4 < kcols)
                v = *(const float4*)(A + (size_t)gr * lda + kbase + c4 * 4);
            int off = r * 128 + ((c4 * 8) ^ ((r & 7) << 4));
            store_hilo(sm, off, v);
        }
        __syncthreads();

        // ---- compute ----
        for (int ks = 0; ks < ksteps; ks++) {
            uint32_t ah[2][4], al[2][4];
            {
                const int rr = (lane & 15);
                const int colb = ks * 32 + (lane & 16);
#pragma unroll
                for (int mt = 0; mt < 2; mt++) {
                    const int row = wm * 32 + mt * 16 + rr;
                    const uint32_t ad = (uint32_t)(row * 128 + (colb ^ ((row & 7) << 4)));
                    ldsm4(ah[mt], sb + SM_A_HI + ad);
                    ldsm4(al[mt], sb + SM_A_LO + ad);
                }
            }
#pragma unroll
            for (int np = 0; np < 4; np++) {
                const int nb = wn * 64 + np * 16;
                const int n = nb + (lane & 7) + ((lane & 16) >> 1);
                const int colb = ks * 32 + ((lane & 8) << 1);
                const uint32_t bd = (uint32_t)(n * 128 + (colb ^ ((n & 7) << 4)));
                uint32_t bh[4], bl[4];
                ldsm4(bh, sb + SM_B_HI + bd);
                ldsm4(bl, sb + SM_B_LO + bd);
#pragma unroll
                for (int mt = 0; mt < 2; mt++) {
#pragma unroll
                    for (int nt = 0; nt < 2; nt++) {
                        float* c = acc[mt][np * 2 + nt];
                        mma16816(c, ah[mt], bh[nt * 2], bh[nt * 2 + 1]);
                        mma16816(c, ah[mt], bl[nt * 2], bl[nt * 2 + 1]);
                        mma16816(c, al[mt], bh[nt * 2], bh[nt * 2 + 1]);
                    }
                }
            }
        }
        __syncthreads();
    }

    // ---- epilogue ----
    const int quad = lane >> 2;
    const int tq = lane & 3;
#pragma unroll
    for (int mt = 0; mt < 2; mt++) {
#pragma unroll
        for (int half = 0; half < 2; half++) {
            const int gr = row0 + wm * 32 + mt * 16 + half * 8 + quad;
            if (gr >= M) continue;
            if (mode == 0) {
                float* po = out + (size_t)gr * ostride + colofs + wn * 64;
                float* pa = (aux && gr < rows_aux)
                          ? aux + (size_t)gr * 512 + aofs + wn * 64 : nullptr;
#pragma unroll
                for (int j = 0; j < 8; j++) {
                    const int col = j * 8 + tq * 2;
                    float c0 = acc[mt][j][half * 2 + 0] + __ldg(bias + wn * 64 + col);
                    float c1 = acc[mt][j][half * 2 + 1] + __ldg(bias + wn * 64 + col + 1);
                    float2 o;
                    o.x = act ? leaky(c0) : c0;
                    o.y = act ? leaky(c1) : c1;
                    *(float2*)(po + col) = o;
                    if (pa) *(float2*)(pa + col) = o;
                }
            } else {
                const float id = __ldg(inv + gr);
                const float dg = __ldg(dis + gr);
                __half2* pi = ibuf + (size_t)gr * 64 + wn * 32;
                __half2* py = ybuf + (size_t)gr * 64 + wn * 32;
#pragma unroll
                for (int j = 0; j < 8; j++) {
                    const int col = j * 8 + tq * 2;
                    float xl0 = acc[mt][j][half * 2 + 0] + __ldg(bias + wn * 64 + col);
                    float xl1 = acc[mt][j][half * 2 + 1] + __ldg(bias + wn * 64 + col + 1);
                    pi[col >> 1] = __floats2half2_rn(
                        relu_(xl0 + __ldg(root + wn * 64 + col)) * id,
                        relu_(xl1 + __ldg(root + wn * 64 + col + 1)) * id);
                    py[col >> 1] = __floats2half2_rn(dg * relu_(xl0), dg * relu_(xl1));
                }
            }
        }
    }
}

// ---------------------------------------------------------------------------
// CSR gather: warp-cooperative src prefetch + 4-wide independent y loads.
// All lanes of the warp handle the same destination (lane = feature group).
// ---------------------------------------------------------------------------
__device__ __forceinline__ void acc_y(float4& na, uint2 v) {
    float2 a0 = __half22float2(*(const __half2*)&v.x);
    float2 a1 = __half22float2(*(const __half2*)&v.y);
    na.x += a0.x; na.y += a0.y; na.z += a1.x; na.w += a1.y;
}

__device__ __forceinline__ float4 gather_sum(const __half2* __restrict__ y,
                                             const int* __restrict__ src,
                                             int o, int k, int lane) {
    float4 n0 = make_float4(0.f, 0.f, 0.f, 0.f);
    float4 n1 = make_float4(0.f, 0.f, 0.f, 0.f);
    for (int base = 0; base < k; base += 32) {
        const int kk = min(32, k - base);
        // one coalesced load fetches up to 32 src indices for this warp
        int myidx = 0;
        if (lane < kk) myidx = __ldg(src + o + base + lane);
        int j = 0;
        for (; j + 4 <= kk; j += 4) {
            const int s0 = __shfl_sync(0xffffffffu, myidx, j + 0);
            const int s1 = __shfl_sync(0xffffffffu, myidx, j + 1);
            const int s2 = __shfl_sync(0xffffffffu, myidx, j + 2);
            const int s3 = __shfl_sync(0xffffffffu, myidx, j + 3);
            const uint2 v0 = *(const uint2*)(y + (size_t)s0 * 64 + lane * 2);
            const uint2 v1 = *(const uint2*)(y + (size_t)s1 * 64 + lane * 2);
            const uint2 v2 = *(const uint2*)(y + (size_t)s2 * 64 + lane * 2);
            const uint2 v3 = *(const uint2*)(y + (size_t)s3 * 64 + lane * 2);
            acc_y(n0, v0); acc_y(n1, v1); acc_y(n0, v2); acc_y(n1, v3);
        }
        if (j + 2 <= kk) {
            const int s0 = __shfl_sync(0xffffffffu, myidx, j + 0);
            const int s1 = __shfl_sync(0xffffffffu, myidx, j + 1);
            const uint2 v0 = *(const uint2*)(y + (size_t)s0 * 64 + lane * 2);
            const uint2 v1 = *(const uint2*)(y + (size_t)s1 * 64 + lane * 2);
            acc_y(n0, v0); acc_y(n1, v1);
            j += 2;
        }
        if (j < kk) {
            const int s0 = __shfl_sync(0xffffffffu, myidx, j);
            const uint2 v0 = *(const uint2*)(y + (size_t)s0 * 64 + lane * 2);
            acc_y(n0, v0);
        }
    }
    n0.x += n1.x; n0.y += n1.y; n0.z += n1.z; n0.w += n1.w;
    return n0;
}

__device__ __forceinline__ float4 load_init_h(const __half2* __restrict__ ibuf,
                                              int c, int lane) {
    const uint2 iv = *(const uint2*)(ibuf + (size_t)c * 64 + lane * 2);
    float2 i0 = __half22float2(*(const __half2*)&iv.x);
    float2 i1 = __half22float2(*(const __half2*)&iv.y);
    return make_float4(i0.x, i0.y, i1.x, i1.y);
}

// ---------------------------------------------------------------------------
// Pass-A aggregation: agg[c] = init[c] + dis[c] * sum YA[src]   (fp32 out)
// ---------------------------------------------------------------------------
__global__ void agg_kernel(const __half2* __restrict__ ibuf,
                           const __half2* __restrict__ y,
                           const int* __restrict__ offs,
                           const int* __restrict__ cnt,
                           const int* __restrict__ src,
                           const float* __restrict__ dis,
                           float* __restrict__ agg, int Nn, int obase) {
    const int c = blockIdx.x * 8 + (threadIdx.x >> 5);
    if (c >= Nn) return;
    const int lane = threadIdx.x & 31;

    float4 acc = load_init_h(ibuf, c, lane);
    const int o = __ldg(offs + obase + c);
    const int k = __ldg(cnt + obase + c);
    const float dc = __ldg(dis + c);
    float4 na = gather_sum(y, src, o, k, lane);
    acc.x += dc * na.x; acc.y += dc * na.y;
    acc.z += dc * na.z; acc.w += dc * na.w;
    ((float4*)agg)[(size_t)c * 32 + lane] = acc;
}

// ---------------------------------------------------------------------------
// Pass-B aggregation + LayerNorm + LeakyReLU + residual.
// ---------------------------------------------------------------------------
__global__ void agg_ln_kernel(const __half2* __restrict__ ibuf,
                              const __half2* __restrict__ y,
                              const int* __restrict__ offs,
                              const int* __restrict__ cnt,
                              const int* __restrict__ src,
                              const float* __restrict__ dis,
                              const float* __restrict__ g,
                              const float* __restrict__ b,
                              const float* __restrict__ hprev,
                              float* __restrict__ hnext, int hstride, int hofs,
                              float* __restrict__ aux, int aofs, int rows_aux,
                              int Nn, int obase) {
    const int c = blockIdx.x * 8 + (threadIdx.x >> 5);
    if (c >= Nn) return;
    const int lane = threadIdx.x & 31;

    float4 acc = load_init_h(ibuf, c, lane);
    const int o = __ldg(offs + obase + c);
    const int k = __ldg(cnt + obase + c);
    const float dc = __ldg(dis + c);
    float4 na = gather_sum(y, src, o, k, lane);
    acc.x += dc * na.x; acc.y += dc * na.y;
    acc.z += dc * na.z; acc.w += dc * na.w;

    float s1 = acc.x + acc.y + acc.z + acc.w;
#pragma unroll
    for (int off = 16; off > 0; off >>= 1) s1 += __shfl_xor_sync(0xffffffffu, s1, off);
    const float mu = s1 * (1.0f / 128.0f);
    float dx = acc.x - mu, dy = acc.y - mu, dz = acc.z - mu, dw = acc.w - mu;
    float q = dx * dx + dy * dy + dz * dz + dw * dw;
#pragma unroll
    for (int off = 16; off > 0; off >>= 1) q += __shfl_xor_sync(0xffffffffu, q, off);
    const float rstd = rsqrtf(q * (1.0f / 128.0f) + LN_EPS);

    float4 gg = ((const float4*)g)[lane];
    float4 bb = ((const float4*)b)[lane];
    float4 hp = ((const float4*)hprev)[(size_t)c * 32 + lane];
    float4 out;
    out.x = leaky(dx * rstd * gg.x + bb.x) + hp.x;
    out.y = leaky(dy * rstd * gg.y + bb.y) + hp.y;
    out.z = leaky(dz * rstd * gg.z + bb.z) + hp.z;
    out.w = leaky(dw * rstd * gg.w + bb.w) + hp.w;
    ((float4*)(hnext + (size_t)c * hstride + hofs))[lane] = out;
    if (aux && c < rows_aux)
        ((float4*)(aux + (size_t)c * 512 + aofs))[lane] = out;
}

// ---------------------------------------------------------------------------
// Launch
// ---------------------------------------------------------------------------
extern "C" void kernel_launch(void* const* d_in, const int* in_sizes, int n_in,
                              void* d_out, int out_size) {
    const float* x        = (const float*)d_in[0];
    const float* enc_w1   = (const float*)d_in[1];
    const float* enc_b1   = (const float*)d_in[2];
    const float* enc_w2   = (const float*)d_in[3];
    const float* enc_b2   = (const float*)d_in[4];
    const float* conv_w   = (const float*)d_in[5];
    const float* conv_b   = (const float*)d_in[6];
    const float* conv_rt  = (const float*)d_in[7];
    const float* reconv_w = (const float*)d_in[8];
    const float* reconv_b = (const float*)d_in[9];
    const float* reconv_rt= (const float*)d_in[10];
    const float* ln_g     = (const float*)d_in[11];
    const float* ln_b     = (const float*)d_in[12];
    const int*   eA       = (const int*)d_in[13];
    const int*   eB       = (const int*)d_in[14];

    const int N  = in_sizes[0] / 32;
    const int Ea = in_sizes[13] / 2;
    const int Eb = in_sizes[14] / 2;
    const int rows_out = out_size / 512;

    const int* rowsA = eA; const int* colsA = eA + Ea;
    const int* rowsB = eB; const int* colsB = eB + Eb;

    void* p;
    cudaGetSymbolAddress(&p, g_H);    float* H    = (float*)p;
    cudaGetSymbolAddress(&p, g_AGG);  float* AGG  = (float*)p;
    cudaGetSymbolAddress(&p, g_H1);   float* H1E  = (float*)p;
    cudaGetSymbolAddress(&p, g_YA);   __half2* YA = (__half2*)p;
    cudaGetSymbolAddress(&p, g_YB);   __half2* YB = (__half2*)p;
    cudaGetSymbolAddress(&p, g_IN);   __half2* IN = (__half2*)p;
    cudaGetSymbolAddress(&p, g_disA); float* disA = (float*)p;
    cudaGetSymbolAddress(&p, g_disB); float* disB = (float*)p;
    cudaGetSymbolAddress(&p, g_invA); float* invA = (float*)p;
    cudaGetSymbolAddress(&p, g_invB); float* invB = (float*)p;
    cudaGetSymbolAddress(&p, g_icsr); int* icsr   = (int*)p;
    cudaGetSymbolAddress(&p, g_offs); int* offs   = (int*)p;
    cudaGetSymbolAddress(&p, g_src);  int* src    = (int*)p;
    cudaGetSymbolAddress(&p, g_bsums);int* bsums  = (int*)p;
    cudaGetSymbolAddress(&p, g_Bhi);  __nv_bfloat16* BH = (__nv_bfloat16*)p;
    cudaGetSymbolAddress(&p, g_Blo);  __nv_bfloat16* BL = (__nv_bfloat16*)p;

    int* rowcntA = icsr;
    int* rowcntB = icsr + NMAX;
    int* colcnt  = icsr + 2 * NMAX;
    int* cursor  = icsr + 4 * NMAX;

    const size_t hstride = (size_t)NMAX * EMB;
    float* dout = (float*)d_out;

    cudaFuncSetAttribute(gemm_tc_kernel,
                         cudaFuncAttributeMaxDynamicSharedMemorySize, SMEM_TC);

    // ---- side stream for the CSR build (overlaps with encoder GEMMs) ----
    static cudaStream_t s2 = nullptr;
    static cudaEvent_t ev_fork = nullptr, ev_join = nullptr;
    if (!s2) {
        cudaStreamCreateWithFlags(&s2, cudaStreamNonBlocking);
        cudaEventCreateWithFlags(&ev_fork, cudaEventDisableTiming);
        cudaEventCreateWithFlags(&ev_join, cudaEventDisableTiming);
    }

    cudaEventRecord(ev_fork, 0);
    cudaStreamWaitEvent(s2, ev_fork, 0);

    // ---- CSR build + degrees (side stream) ----
    zero_kernel<<<(6 * NMAX + 255) / 256, 256, 0, s2>>>(icsr, 6 * NMAX);
    hist2_kernel<<<(Ea + 255) / 256, 256, 0, s2>>>(rowsA, colsA, rowcntA, colcnt, Ea);
    hist2_kernel<<<(Eb + 255) / 256, 256, 0, s2>>>(rowsB, colsB, rowcntB,
                                                   colcnt + NMAX, Eb);
    deg_fin_kernel<<<(N + 255) / 256, 256, 0, s2>>>(rowcntA, disA, invA, N);
    deg_fin_kernel<<<(N + 255) / 256, 256, 0, s2>>>(rowcntB, disB, invB, N);
    {
        const int n2 = 2 * NMAX;
        const int nb = (n2 + 1023) / 1024;
        scan_block_kernel<<<nb, 256, 0, s2>>>(colcnt, offs, bsums, n2);
        scan_sums_kernel<<<1, 512, 0, s2>>>(bsums, nb);
        scan_add_kernel<<<(n2 + 255) / 256, 256, 0, s2>>>(offs, bsums, n2);
    }
    fill_kernel<<<(Ea + 255) / 256, 256, 0, s2>>>(rowsA, colsA, offs, cursor, src,
                                                  Ea, 0);
    fill_kernel<<<(Eb + 255) / 256, 256, 0, s2>>>(rowsB, colsB, offs, cursor, src,
                                                  Eb, NMAX);
    cudaEventRecord(ev_join, s2);

    // ---- weight prep + encoder (main stream, concurrent with CSR build) ----
    prep_all_kernel<<<18 * 32, 256>>>(enc_w1, enc_w2, conv_w, reconv_w, BH, BL);

    const int tiles = (N + 127) / 128;

    gemm_tc_kernel<<<tiles, 256, SMEM_TC>>>(x, 32, N,
        BH + 0 * 8192, BL + 0 * 8192, 1, 32, enc_b1, H1E, 256, 0, 1,
        nullptr, 0, 0, 0, nullptr, nullptr, nullptr, nullptr, nullptr);
    gemm_tc_kernel<<<tiles, 256, SMEM_TC>>>(x, 32, N,
        BH + 1 * 8192, BL + 1 * 8192, 1, 32, enc_b1 + 128, H1E, 256, 128, 1,
        nullptr, 0, 0, 0, nullptr, nullptr, nullptr, nullptr, nullptr);
    gemm_tc_kernel<<<tiles, 256, SMEM_TC>>>(H1E, 256, N,
        BH + 2 * 8192, BL + 2 * 8192, 4, 256, enc_b2, H, 128, 0, 1,
        dout, 0, rows_out, 0, nullptr, nullptr, nullptr, nullptr, nullptr);

    // join: GCN layers need the CSR
    cudaStreamWaitEvent(0, ev_join, 0);

    // ---- GCN layers ----
    for (int l = 0; l < 3; l++) {
        const float* hl = H + (size_t)l * hstride;
        float* hn = H + (size_t)(l + 1) * hstride;
        const int last = (l == 2);

        // conv (edge set A): GEMM -> IN (half init) + YA
        gemm_tc_kernel<<<tiles, 256, SMEM_TC>>>(hl, 128, N,
            BH + (6 + 2 * l) * 8192, BL + (6 + 2 * l) * 8192, 2, 128,
            conv_b + l * EMB, nullptr, 0, 0, 0,
            nullptr, 0, 0, 1, conv_rt + l * EMB, disA, invA, YA, IN);
        agg_kernel<<<(N + 7) / 8, 256>>>(IN, YA, offs, colcnt, src, disA, AGG, N, 0);

        // reconv (edge set B): GEMM reads AGG -> IN (half init, reused) + YB
        gemm_tc_kernel<<<tiles, 256, SMEM_TC>>>(AGG, 128, N,
            BH + (12 + 2 * l) * 8192, BL + (12 + 2 * l) * 8192, 2, 128,
            reconv_b + l * EMB, nullptr, 0, 0, 0,
            nullptr, 0, 0, 1, reconv_rt + l * EMB, disB, invB, YB, IN);

        if (!last) {
            agg_ln_kernel<<<(N + 7) / 8, 256>>>(IN, YB, offs, colcnt, src, disB,
                ln_g + l * EMB, ln_b + l * EMB, hl,
                hn, 128, 0, dout, (l + 1) * 128, rows_out, N, NMAX);
        } else {
            agg_ln_kernel<<<(rows_out + 7) / 8, 256>>>(IN, YB, offs, colcnt, src, disB,
                ln_g + l * EMB, ln_b + l * EMB, hl,
                dout, 512, 384, nullptr, 0, 0, rows_out, NMAX);
        }
    }
}

// round 14
// speedup vs baseline: 1.1456x; 1.1456x over previous
#include <cuda_runtime.h>
#include <cuda_bf16.h>
#include <cuda_fp16.h>
#include <cstddef>
#include <cstdint>

// ---------------------------------------------------------------------------
// Problem constants
// ---------------------------------------------------------------------------
#define NMAX   200000
#define EMAX   650000
#define EMB    128
#define ENC1   256
#define NEG_SLOPE 0.1f
#define LN_EPS 1e-5f

// ---------------------------------------------------------------------------
// Scratch (static __device__ arrays; no allocations allowed)
// ---------------------------------------------------------------------------
__device__ float g_H[4][(size_t)NMAX * EMB];   // h_list[0..3]
__device__ float g_AGG[(size_t)NMAX * EMB];    // pass-A aggregated output (fp32)
__device__ float g_H1[(size_t)NMAX * ENC1];    // encoder intermediate
__device__ __half2 g_YA[(size_t)NMAX * 64];    // fp16 messages, pass A
__device__ __half2 g_YB[(size_t)NMAX * 64];    // fp16 messages, pass B
__device__ __half2 g_IN[(size_t)NMAX * 64];    // fp16 init (self term), reused A/B
__device__ float g_disA[NMAX];
__device__ float g_disB[NMAX];
__device__ float g_invA[NMAX];
__device__ float g_invB[NMAX];
// CSR scratch: [0,N) rowcntA | [N,2N) rowcntB | [2N,4N) colcnt (A then B)
//              [4N,6N) cursors (A then B)
__device__ int g_icsr[6 * NMAX];
__device__ int g_offs[2 * NMAX];
__device__ int g_src[2 * EMAX];
__device__ int g_bsums[512];
// Prepped weight chunks: 18 chunks of [128 n x 64 k] bf16, XOR-swizzled, hi/lo.
__device__ __nv_bfloat16 g_Bhi[18 * 8192];
__device__ __nv_bfloat16 g_Blo[18 * 8192];

// ---------------------------------------------------------------------------
// Helpers
// ---------------------------------------------------------------------------
__device__ __forceinline__ float leaky(float v) {
    return v >= 0.0f ? v : NEG_SLOPE * v;
}
__device__ __forceinline__ float relu_(float v) { return fmaxf(v, 0.0f); }

__device__ __forceinline__ uint32_t smem_u32(const void* p) {
    uint32_t a;
    asm("{ .reg .u64 t; cvta.to.shared.u64 t, %1; cvt.u32.u64 %0, t; }"
        : "=r"(a) : "l"(p));
    return a;
}

__device__ __forceinline__ void ldsm4(uint32_t* r, uint32_t addr) {
    asm volatile("ldmatrix.sync.aligned.m8n8.x4.shared.b16 {%0,%1,%2,%3}, [%4];"
                 : "=r"(r[0]), "=r"(r[1]), "=r"(r[2]), "=r"(r[3]) : "r"(addr));
}

__device__ __forceinline__ void mma16816(float* c, const uint32_t* a,
                                         uint32_t b0, uint32_t b1) {
    asm volatile(
        "mma.sync.aligned.m16n8k16.row.col.f32.bf16.bf16.f32 "
        "{%0,%1,%2,%3}, {%4,%5,%6,%7}, {%8,%9}, {%0,%1,%2,%3};"
        : "+f"(c[0]), "+f"(c[1]), "+f"(c[2]), "+f"(c[3])
        : "r"(a[0]), "r"(a[1]), "r"(a[2]), "r"(a[3]), "r"(b0), "r"(b1));
}

// fp32x4 -> swizzled bf16 hi/lo store (packed converts)
__device__ __forceinline__ void store_hilo(char* smbase, int off, float4 v) {
    __nv_bfloat162 h01 = __float22bfloat162_rn(make_float2(v.x, v.y));
    __nv_bfloat162 h23 = __float22bfloat162_rn(make_float2(v.z, v.w));
    float2 hf01 = __bfloat1622float2(h01);
    float2 hf23 = __bfloat1622float2(h23);
    __nv_bfloat162 l01 = __float22bfloat162_rn(make_float2(v.x - hf01.x, v.y - hf01.y));
    __nv_bfloat162 l23 = __float22bfloat162_rn(make_float2(v.z - hf23.x, v.w - hf23.y));
    uint2 hi = make_uint2(*reinterpret_cast<uint32_t*>(&h01),
                          *reinterpret_cast<uint32_t*>(&h23));
    uint2 lo = make_uint2(*reinterpret_cast<uint32_t*>(&l01),
                          *reinterpret_cast<uint32_t*>(&l23));
    *(uint2*)(smbase + 0     + off) = hi;   // SM_A_HI == 0
    *(uint2*)(smbase + 16384 + off) = lo;   // SM_A_LO == 16384
}

// ---------------------------------------------------------------------------
// CSR build kernels
// ---------------------------------------------------------------------------
__global__ void zero_kernel(int* p, int n) {
    int i = blockIdx.x * blockDim.x + threadIdx.x;
    if (i < n) p[i] = 0;
}

__global__ void hist2_kernel(const int* __restrict__ rows,
                             const int* __restrict__ cols,
                             int* __restrict__ rowcnt,
                             int* __restrict__ colcnt, int E) {
    int e = blockIdx.x * blockDim.x + threadIdx.x;
    if (e >= E) return;
    atomicAdd(&rowcnt[rows[e]], 1);
    atomicAdd(&colcnt[cols[e]], 1);
}

__global__ void deg_fin_kernel(const int* __restrict__ cnt,
                               float* __restrict__ dis,
                               float* __restrict__ inv, int n) {
    int i = blockIdx.x * blockDim.x + threadIdx.x;
    if (i < n) {
        float d = (float)(cnt[i] + 1);
        dis[i] = rsqrtf(d);
        inv[i] = 1.0f / d;
    }
}

__global__ void scan_block_kernel(const int* __restrict__ in, int* __restrict__ out,
                                  int* __restrict__ bsums, int n) {
    __shared__ int sh[256];
    const int base = blockIdx.x * 1024;
    const int t = threadIdx.x;
    int v[4]; int s = 0;
#pragma unroll
    for (int j = 0; j < 4; j++) {
        int i = base + t * 4 + j;
        v[j] = (i < n) ? in[i] : 0;
        s += v[j];
    }
    sh[t] = s;
    __syncthreads();
    for (int off = 1; off < 256; off <<= 1) {
        int x = (t >= off) ? sh[t - off] : 0;
        __syncthreads();
        sh[t] += x;
        __syncthreads();
    }
    int run = (t > 0) ? sh[t - 1] : 0;
    if (t == 255) bsums[blockIdx.x] = sh[255];
#pragma unroll
    for (int j = 0; j < 4; j++) {
        int i = base + t * 4 + j;
        if (i < n) out[i] = run;
        run += v[j];
    }
}

__global__ void scan_sums_kernel(int* bsums, int nb) {
    __shared__ int sh[512];
    int t = threadIdx.x;
    sh[t] = (t < nb) ? bsums[t] : 0;
    __syncthreads();
    for (int off = 1; off < 512; off <<= 1) {
        int x = (t >= off) ? sh[t - off] : 0;
        __syncthreads();
        sh[t] += x;
        __syncthreads();
    }
    if (t < nb) bsums[t] = (t > 0) ? sh[t - 1] : 0;
}

__global__ void scan_add_kernel(int* __restrict__ out, const int* __restrict__ bsums,
                                int n) {
    int i = blockIdx.x * blockDim.x + threadIdx.x;
    if (i < n) out[i] += bsums[i >> 10];
}

__global__ void fill_kernel(const int* __restrict__ rows, const int* __restrict__ cols,
                            const int* __restrict__ offs, int* __restrict__ cursor,
                            int* __restrict__ src, int E, int obase) {
    int e = blockIdx.x * blockDim.x + threadIdx.x;
    if (e >= E) return;
    int c = cols[e];
    int pos = offs[obase + c] + atomicAdd(&cursor[obase + c], 1);
    src[pos] = rows[e];
}

// ---------------------------------------------------------------------------
// Merged weight prep: 18 chunks of [128n x 64k], swizzled bf16 hi/lo
// ---------------------------------------------------------------------------
__global__ void prep_all_kernel(const float* __restrict__ enc_w1,
                                const float* __restrict__ enc_w2,
                                const float* __restrict__ conv_w,
                                const float* __restrict__ reconv_w,
                                __nv_bfloat16* __restrict__ BH,
                                __nv_bfloat16* __restrict__ BL) {
    const int chunk = blockIdx.x >> 5;
    const int idx = (blockIdx.x & 31) * 256 + threadIdx.x;
    const int n = idx >> 6;
    const int k = idx & 63;
    const float* W; int ldn, k0, n0, kcount;
    if (chunk < 2)      { W = enc_w1; ldn = 256; k0 = 0; n0 = chunk * 128; kcount = 32; }
    else if (chunk < 6) { W = enc_w2; ldn = 128; k0 = (chunk - 2) * 64; n0 = 0; kcount = 64; }
    else if (chunk < 12) {
        int l = (chunk - 6) >> 1, c = (chunk - 6) & 1;
        W = conv_w + (size_t)l * 16384; ldn = 128; k0 = c * 64; n0 = 0; kcount = 64;
    } else {
        int l = (chunk - 12) >> 1, c = (chunk - 12) & 1;
        W = reconv_w + (size_t)l * 16384; ldn = 128; k0 = c * 64; n0 = 0; kcount = 64;
    }
    float v = (k < kcount) ? W[(size_t)(k0 + k) * ldn + n0 + n] : 0.0f;
    __nv_bfloat16 h = __float2bfloat16(v);
    __nv_bfloat16 l = __float2bfloat16(v - __bfloat162float(h));
    int off = n * 128 + ((k * 2) ^ ((n & 7) << 4));
    BH[(size_t)chunk * 8192 + (off >> 1)] = h;
    BL[(size_t)chunk * 8192 + (off >> 1)] = l;
}

// ---------------------------------------------------------------------------
// Tensor-core GEMM (mma.sync bf16 3-split): d = A[M,KV] @ W + bias
//  mode 0: out[gr*ostride+colofs+n] = act? leaky(d) : d
//          if (aux && gr<rows_aux) also aux[gr*512+aofs+n]
//  mode 1 (GCN prep): ibuf[gr][n] = half( relu(d+root[n]) * inv[gr] )  (init)
//                     ybuf[gr][n] = half( dis[gr] * relu(d) )          (message)
//  Optional second half (Bhi2 != null, requires kchunks==1, mode 0):
//    after the first epilogue, re-stage B from (Bhi2,Blo2) with the A tile
//    still resident in SMEM, recompute, epilogue at colofs2 with bias2.
// ---------------------------------------------------------------------------
#define SM_A_HI 0
#define SM_A_LO 16384
#define SM_B_HI 32768
#define SM_B_LO 49152
#define SMEM_TC 65536

struct EpiArgs {
    const float* bias; float* out; int ostride; int colofs; int act;
    float* aux; int aofs; int rows_aux;
};

__global__ void __launch_bounds__(256, 2)
gemm_tc_kernel(const float* __restrict__ A, int lda, int M,
               const __nv_bfloat16* __restrict__ BhiG,
               const __nv_bfloat16* __restrict__ BloG,
               int kchunks, int KV,
               const float* __restrict__ bias,
               float* __restrict__ out, int ostride, int colofs, int act,
               float* __restrict__ aux, int aofs, int rows_aux,
               int mode,
               const float* __restrict__ root,
               const float* __restrict__ dis,
               const float* __restrict__ inv,
               __half2* __restrict__ ybuf,
               __half2* __restrict__ ibuf,
               const __nv_bfloat16* __restrict__ Bhi2,
               const __nv_bfloat16* __restrict__ Blo2,
               const float* __restrict__ bias2, int colofs2) {
    extern __shared__ char sm[];
    const uint32_t sb = smem_u32(sm);
    const int tid = threadIdx.x;
    const int w = tid >> 5;
    const int lane = tid & 31;
    const int wm = w & 3;
    const int wn = w >> 2;
    const int row0 = blockIdx.x * 128;
    const int nhalves = Bhi2 ? 2 : 1;

    for (int half = 0; half < nhalves; half++) {
        const __nv_bfloat16* BhiH = half ? Bhi2 : BhiG;
        const __nv_bfloat16* BloH = half ? Blo2 : BloG;
        const float* biasH = half ? bias2 : bias;
        const int colofsH = half ? colofs2 : colofs;

        float acc[2][8][4];
#pragma unroll
        for (int a = 0; a < 2; a++)
#pragma unroll
            for (int b = 0; b < 8; b++)
#pragma unroll
                for (int c = 0; c < 4; c++) acc[a][b][c] = 0.0f;

        for (int ck = 0; ck < kchunks; ck++) {
            const int kbase = ck * 64;
            int kcols = KV - kbase; if (kcols > 64) kcols = 64;
            const int ksteps = (kcols + 15) >> 4;

            if (half > 0) __syncthreads();   // protect B buffer reuse

            // ---- stage B chunk ----
            {
                const float4* shg = (const float4*)(BhiH + (size_t)ck * 8192);
                const float4* slg = (const float4*)(BloH + (size_t)ck * 8192);
                float4* dh = (float4*)(sm + SM_B_HI);
                float4* dl = (float4*)(sm + SM_B_LO);
                for (int i = tid; i < 1024; i += 256) { dh[i] = shg[i]; dl[i] = slg[i]; }
            }

            // ---- stage A chunk [128 x 64] fp32 -> bf16 hi/lo (half 0 only) ----
            if (half == 0) {
#pragma unroll
                for (int i = 0; i < 8; i++) {
                    const int idx = tid + i * 256;
                    const int r = idx >> 4;
                    const int c4 = idx & 15;
                    float4 v = make_float4(0.f, 0.f, 0.f, 0.f);
                    const int gr = row0 + r;
                    if (gr < M && c4 * 4 < kcols)
                        v = *(const float4*)(A + (size_t)gr * lda + kbase + c4 * 4);
                    int off = r * 128 + ((c4 * 8) ^ ((r & 7) << 4));
                    store_hilo(sm, off, v);
                }
            }
            __syncthreads();

            // ---- compute ----
            for (int ks = 0; ks < ksteps; ks++) {
                uint32_t ah[2][4], al[2][4];
                {
                    const int rr = (lane & 15);
                    const int colb = ks * 32 + (lane & 16);
#pragma unroll
                    for (int mt = 0; mt < 2; mt++) {
                        const int row = wm * 32 + mt * 16 + rr;
                        const uint32_t ad = (uint32_t)(row * 128 +
                                           (colb ^ ((row & 7) << 4)));
                        ldsm4(ah[mt], sb + SM_A_HI + ad);
                        ldsm4(al[mt], sb + SM_A_LO + ad);
                    }
                }
#pragma unroll
                for (int np = 0; np < 4; np++) {
                    const int nb = wn * 64 + np * 16;
                    const int n = nb + (lane & 7) + ((lane & 16) >> 1);
                    const int colb = ks * 32 + ((lane & 8) << 1);
                    const uint32_t bd = (uint32_t)(n * 128 + (colb ^ ((n & 7) << 4)));
                    uint32_t bh[4], bl[4];
                    ldsm4(bh, sb + SM_B_HI + bd);
                    ldsm4(bl, sb + SM_B_LO + bd);
#pragma unroll
                    for (int mt = 0; mt < 2; mt++) {
#pragma unroll
                        for (int nt = 0; nt < 2; nt++) {
                            float* c = acc[mt][np * 2 + nt];
                            mma16816(c, ah[mt], bh[nt * 2], bh[nt * 2 + 1]);
                            mma16816(c, ah[mt], bl[nt * 2], bl[nt * 2 + 1]);
                            mma16816(c, al[mt], bh[nt * 2], bh[nt * 2 + 1]);
                        }
                    }
                }
            }
            __syncthreads();
        }

        // ---- epilogue ----
        const int quad = lane >> 2;
        const int tq = lane & 3;
#pragma unroll
        for (int mt = 0; mt < 2; mt++) {
#pragma unroll
            for (int half8 = 0; half8 < 2; half8++) {
                const int gr = row0 + wm * 32 + mt * 16 + half8 * 8 + quad;
                if (gr >= M) continue;
                if (mode == 0) {
                    float* po = out + (size_t)gr * ostride + colofsH + wn * 64;
                    float* pa = (aux && gr < rows_aux)
                              ? aux + (size_t)gr * 512 + aofs + wn * 64 : nullptr;
#pragma unroll
                    for (int j = 0; j < 8; j++) {
                        const int col = j * 8 + tq * 2;
                        float c0 = acc[mt][j][half8 * 2 + 0] + __ldg(biasH + wn * 64 + col);
                        float c1 = acc[mt][j][half8 * 2 + 1] + __ldg(biasH + wn * 64 + col + 1);
                        float2 o;
                        o.x = act ? leaky(c0) : c0;
                        o.y = act ? leaky(c1) : c1;
                        *(float2*)(po + col) = o;
                        if (pa) *(float2*)(pa + col) = o;
                    }
                } else {
                    const float id = __ldg(inv + gr);
                    const float dg = __ldg(dis + gr);
                    __half2* pi = ibuf + (size_t)gr * 64 + wn * 32;
                    __half2* py = ybuf + (size_t)gr * 64 + wn * 32;
#pragma unroll
                    for (int j = 0; j < 8; j++) {
                        const int col = j * 8 + tq * 2;
                        float xl0 = acc[mt][j][half8 * 2 + 0] + __ldg(bias + wn * 64 + col);
                        float xl1 = acc[mt][j][half8 * 2 + 1] + __ldg(bias + wn * 64 + col + 1);
                        pi[col >> 1] = __floats2half2_rn(
                            relu_(xl0 + __ldg(root + wn * 64 + col)) * id,
                            relu_(xl1 + __ldg(root + wn * 64 + col + 1)) * id);
                        py[col >> 1] = __floats2half2_rn(dg * relu_(xl0), dg * relu_(xl1));
                    }
                }
            }
        }
    }
}

// ---------------------------------------------------------------------------
// CSR gather helpers (R12 version — empirically best at avg degree ~3)
// ---------------------------------------------------------------------------
__device__ __forceinline__ float4 gather_sum(const __half2* __restrict__ y,
                                             const int* __restrict__ src,
                                             int o, int k, int lane) {
    float4 na = make_float4(0.f, 0.f, 0.f, 0.f);
    int j = 0;
    for (; j + 2 <= k; j += 2) {
        const int s0 = __ldg(src + o + j);
        const int s1 = __ldg(src + o + j + 1);
        const uint2 v0 = *(const uint2*)(y + (size_t)s0 * 64 + lane * 2);
        const uint2 v1 = *(const uint2*)(y + (size_t)s1 * 64 + lane * 2);
        float2 a0 = __half22float2(*(const __half2*)&v0.x);
        float2 a1 = __half22float2(*(const __half2*)&v0.y);
        float2 b0 = __half22float2(*(const __half2*)&v1.x);
        float2 b1 = __half22float2(*(const __half2*)&v1.y);
        na.x += a0.x + b0.x;
        na.y += a0.y + b0.y;
        na.z += a1.x + b1.x;
        na.w += a1.y + b1.y;
    }
    if (j < k) {
        const int s0 = __ldg(src + o + j);
        const uint2 v0 = *(const uint2*)(y + (size_t)s0 * 64 + lane * 2);
        float2 a0 = __half22float2(*(const __half2*)&v0.x);
        float2 a1 = __half22float2(*(const __half2*)&v0.y);
        na.x += a0.x; na.y += a0.y; na.z += a1.x; na.w += a1.y;
    }
    return na;
}

__device__ __forceinline__ float4 load_init_h(const __half2* __restrict__ ibuf,
                                              int c, int lane) {
    const uint2 iv = *(const uint2*)(ibuf + (size_t)c * 64 + lane * 2);
    float2 i0 = __half22float2(*(const __half2*)&iv.x);
    float2 i1 = __half22float2(*(const __half2*)&iv.y);
    return make_float4(i0.x, i0.y, i1.x, i1.y);
}

// ---------------------------------------------------------------------------
// Pass-A aggregation: agg[c] = init[c] + dis[c] * sum YA[src]   (fp32 out)
// ---------------------------------------------------------------------------
__global__ void agg_kernel(const __half2* __restrict__ ibuf,
                           const __half2* __restrict__ y,
                           const int* __restrict__ offs,
                           const int* __restrict__ cnt,
                           const int* __restrict__ src,
                           const float* __restrict__ dis,
                           float* __restrict__ agg, int Nn, int obase) {
    const int c = blockIdx.x * 8 + (threadIdx.x >> 5);
    if (c >= Nn) return;
    const int lane = threadIdx.x & 31;

    float4 acc = load_init_h(ibuf, c, lane);
    const int o = __ldg(offs + obase + c);
    const int k = __ldg(cnt + obase + c);
    const float dc = __ldg(dis + c);
    float4 na = gather_sum(y, src, o, k, lane);
    acc.x += dc * na.x; acc.y += dc * na.y;
    acc.z += dc * na.z; acc.w += dc * na.w;
    ((float4*)agg)[(size_t)c * 32 + lane] = acc;
}

// ---------------------------------------------------------------------------
// Pass-B aggregation + LayerNorm + LeakyReLU + residual.
// ---------------------------------------------------------------------------
__global__ void agg_ln_kernel(const __half2* __restrict__ ibuf,
                              const __half2* __restrict__ y,
                              const int* __restrict__ offs,
                              const int* __restrict__ cnt,
                              const int* __restrict__ src,
                              const float* __restrict__ dis,
                              const float* __restrict__ g,
                              const float* __restrict__ b,
                              const float* __restrict__ hprev,
                              float* __restrict__ hnext, int hstride, int hofs,
                              float* __restrict__ aux, int aofs, int rows_aux,
                              int Nn, int obase) {
    const int c = blockIdx.x * 8 + (threadIdx.x >> 5);
    if (c >= Nn) return;
    const int lane = threadIdx.x & 31;

    float4 acc = load_init_h(ibuf, c, lane);
    const int o = __ldg(offs + obase + c);
    const int k = __ldg(cnt + obase + c);
    const float dc = __ldg(dis + c);
    float4 na = gather_sum(y, src, o, k, lane);
    acc.x += dc * na.x; acc.y += dc * na.y;
    acc.z += dc * na.z; acc.w += dc * na.w;

    float s1 = acc.x + acc.y + acc.z + acc.w;
#pragma unroll
    for (int off = 16; off > 0; off >>= 1) s1 += __shfl_xor_sync(0xffffffffu, s1, off);
    const float mu = s1 * (1.0f / 128.0f);
    float dx = acc.x - mu, dy = acc.y - mu, dz = acc.z - mu, dw = acc.w - mu;
    float q = dx * dx + dy * dy + dz * dz + dw * dw;
#pragma unroll
    for (int off = 16; off > 0; off >>= 1) q += __shfl_xor_sync(0xffffffffu, q, off);
    const float rstd = rsqrtf(q * (1.0f / 128.0f) + LN_EPS);

    float4 gg = ((const float4*)g)[lane];
    float4 bb = ((const float4*)b)[lane];
    float4 hp = ((const float4*)hprev)[(size_t)c * 32 + lane];
    float4 out;
    out.x = leaky(dx * rstd * gg.x + bb.x) + hp.x;
    out.y = leaky(dy * rstd * gg.y + bb.y) + hp.y;
    out.z = leaky(dz * rstd * gg.z + bb.z) + hp.z;
    out.w = leaky(dw * rstd * gg.w + bb.w) + hp.w;
    ((float4*)(hnext + (size_t)c * hstride + hofs))[lane] = out;
    if (aux && c < rows_aux)
        ((float4*)(aux + (size_t)c * 512 + aofs))[lane] = out;
}

// ---------------------------------------------------------------------------
// Launch
// ---------------------------------------------------------------------------
extern "C" void kernel_launch(void* const* d_in, const int* in_sizes, int n_in,
                              void* d_out, int out_size) {
    const float* x        = (const float*)d_in[0];
    const float* enc_w1   = (const float*)d_in[1];
    const float* enc_b1   = (const float*)d_in[2];
    const float* enc_w2   = (const float*)d_in[3];
    const float* enc_b2   = (const float*)d_in[4];
    const float* conv_w   = (const float*)d_in[5];
    const float* conv_b   = (const float*)d_in[6];
    const float* conv_rt  = (const float*)d_in[7];
    const float* reconv_w = (const float*)d_in[8];
    const float* reconv_b = (const float*)d_in[9];
    const float* reconv_rt= (const float*)d_in[10];
    const float* ln_g     = (const float*)d_in[11];
    const float* ln_b     = (const float*)d_in[12];
    const int*   eA       = (const int*)d_in[13];
    const int*   eB       = (const int*)d_in[14];

    const int N  = in_sizes[0] / 32;
    const int Ea = in_sizes[13] / 2;
    const int Eb = in_sizes[14] / 2;
    const int rows_out = out_size / 512;

    const int* rowsA = eA; const int* colsA = eA + Ea;
    const int* rowsB = eB; const int* colsB = eB + Eb;

    void* p;
    cudaGetSymbolAddress(&p, g_H);    float* H    = (float*)p;
    cudaGetSymbolAddress(&p, g_AGG);  float* AGG  = (float*)p;
    cudaGetSymbolAddress(&p, g_H1);   float* H1E  = (float*)p;
    cudaGetSymbolAddress(&p, g_YA);   __half2* YA = (__half2*)p;
    cudaGetSymbolAddress(&p, g_YB);   __half2* YB = (__half2*)p;
    cudaGetSymbolAddress(&p, g_IN);   __half2* IN = (__half2*)p;
    cudaGetSymbolAddress(&p, g_disA); float* disA = (float*)p;
    cudaGetSymbolAddress(&p, g_disB); float* disB = (float*)p;
    cudaGetSymbolAddress(&p, g_invA); float* invA = (float*)p;
    cudaGetSymbolAddress(&p, g_invB); float* invB = (float*)p;
    cudaGetSymbolAddress(&p, g_icsr); int* icsr   = (int*)p;
    cudaGetSymbolAddress(&p, g_offs); int* offs   = (int*)p;
    cudaGetSymbolAddress(&p, g_src);  int* src    = (int*)p;
    cudaGetSymbolAddress(&p, g_bsums);int* bsums  = (int*)p;
    cudaGetSymbolAddress(&p, g_Bhi);  __nv_bfloat16* BH = (__nv_bfloat16*)p;
    cudaGetSymbolAddress(&p, g_Blo);  __nv_bfloat16* BL = (__nv_bfloat16*)p;

    int* rowcntA = icsr;
    int* rowcntB = icsr + NMAX;
    int* colcnt  = icsr + 2 * NMAX;
    int* cursor  = icsr + 4 * NMAX;

    const size_t hstride = (size_t)NMAX * EMB;
    float* dout = (float*)d_out;

    cudaFuncSetAttribute(gemm_tc_kernel,
                         cudaFuncAttributeMaxDynamicSharedMemorySize, SMEM_TC);

    // ---- side stream for the CSR build (overlaps with encoder GEMMs) ----
    static cudaStream_t s2 = nullptr;
    static cudaEvent_t ev_fork = nullptr, ev_join = nullptr;
    if (!s2) {
        cudaStreamCreateWithFlags(&s2, cudaStreamNonBlocking);
        cudaEventCreateWithFlags(&ev_fork, cudaEventDisableTiming);
        cudaEventCreateWithFlags(&ev_join, cudaEventDisableTiming);
    }

    cudaEventRecord(ev_fork, 0);
    cudaStreamWaitEvent(s2, ev_fork, 0);

    // ---- CSR build + degrees (side stream) ----
    zero_kernel<<<(6 * NMAX + 255) / 256, 256, 0, s2>>>(icsr, 6 * NMAX);
    hist2_kernel<<<(Ea + 255) / 256, 256, 0, s2>>>(rowsA, colsA, rowcntA, colcnt, Ea);
    hist2_kernel<<<(Eb + 255) / 256, 256, 0, s2>>>(rowsB, colsB, rowcntB,
                                                   colcnt + NMAX, Eb);
    deg_fin_kernel<<<(N + 255) / 256, 256, 0, s2>>>(rowcntA, disA, invA, N);
    deg_fin_kernel<<<(N + 255) / 256, 256, 0, s2>>>(rowcntB, disB, invB, N);
    {
        const int n2 = 2 * NMAX;
        const int nb = (n2 + 1023) / 1024;
        scan_block_kernel<<<nb, 256, 0, s2>>>(colcnt, offs, bsums, n2);
        scan_sums_kernel<<<1, 512, 0, s2>>>(bsums, nb);
        scan_add_kernel<<<(n2 + 255) / 256, 256, 0, s2>>>(offs, bsums, n2);
    }
    fill_kernel<<<(Ea + 255) / 256, 256, 0, s2>>>(rowsA, colsA, offs, cursor, src,
                                                  Ea, 0);
    fill_kernel<<<(Eb + 255) / 256, 256, 0, s2>>>(rowsB, colsB, offs, cursor, src,
                                                  Eb, NMAX);
    cudaEventRecord(ev_join, s2);

    // ---- weight prep + encoder (main stream, concurrent with CSR build) ----
    prep_all_kernel<<<18 * 32, 256>>>(enc_w1, enc_w2, conv_w, reconv_w, BH, BL);

    const int tiles = (N + 127) / 128;

    // enc1: single launch covering both N-halves (A tile staged once)
    gemm_tc_kernel<<<tiles, 256, SMEM_TC>>>(x, 32, N,
        BH + 0 * 8192, BL + 0 * 8192, 1, 32, enc_b1, H1E, 256, 0, 1,
        nullptr, 0, 0, 0, nullptr, nullptr, nullptr, nullptr, nullptr,
        BH + 1 * 8192, BL + 1 * 8192, enc_b1 + 128, 128);
    // enc2 -> H0 + JK slice 0 of d_out
    gemm_tc_kernel<<<tiles, 256, SMEM_TC>>>(H1E, 256, N,
        BH + 2 * 8192, BL + 2 * 8192, 4, 256, enc_b2, H, 128, 0, 1,
        dout, 0, rows_out, 0, nullptr, nullptr, nullptr, nullptr, nullptr,
        nullptr, nullptr, nullptr, 0);

    // join: GCN layers need the CSR
    cudaStreamWaitEvent(0, ev_join, 0);

    // ---- GCN layers ----
    for (int l = 0; l < 3; l++) {
        const float* hl = H + (size_t)l * hstride;
        float* hn = H + (size_t)(l + 1) * hstride;
        const int last = (l == 2);

        // conv (edge set A): GEMM -> IN (half init) + YA
        gemm_tc_kernel<<<tiles, 256, SMEM_TC>>>(hl, 128, N,
            BH + (6 + 2 * l) * 8192, BL + (6 + 2 * l) * 8192, 2, 128,
            conv_b + l * EMB, nullptr, 0, 0, 0,
            nullptr, 0, 0, 1, conv_rt + l * EMB, disA, invA, YA, IN,
            nullptr, nullptr, nullptr, 0);
        agg_kernel<<<(N + 7) / 8, 256>>>(IN, YA, offs, colcnt, src, disA, AGG, N, 0);

        // reconv (edge set B): GEMM reads AGG -> IN (half init, reused) + YB
        gemm_tc_kernel<<<tiles, 256, SMEM_TC>>>(AGG, 128, N,
            BH + (12 + 2 * l) * 8192, BL + (12 + 2 * l) * 8192, 2, 128,
            reconv_b + l * EMB, nullptr, 0, 0, 0,
            nullptr, 0, 0, 1, reconv_rt + l * EMB, disB, invB, YB, IN,
            nullptr, nullptr, nullptr, 0);

        if (!last) {
            agg_ln_kernel<<<(N + 7) / 8, 256>>>(IN, YB, offs, colcnt, src, disB,
                ln_g + l * EMB, ln_b + l * EMB, hl,
                hn, 128, 0, dout, (l + 1) * 128, rows_out, N, NMAX);
        } else {
            agg_ln_kernel<<<(rows_out + 7) / 8, 256>>>(IN, YB, offs, colcnt, src, disB,
                ln_g + l * EMB, ln_b + l * EMB, hl,
                dout, 512, 384, nullptr, 0, 0, rows_out, NMAX);
        }
    }
}

// round 15
// speedup vs baseline: 1.1727x; 1.0236x over previous
#include <cuda_runtime.h>
#include <cuda_bf16.h>
#include <cuda_fp16.h>
#include <cstddef>
#include <cstdint>

// ---------------------------------------------------------------------------
// Problem constants
// ---------------------------------------------------------------------------
#define NMAX   200000
#define EMAX   650000
#define EMB    128
#define ENC1   256
#define NEG_SLOPE 0.1f
#define LN_EPS 1e-5f

// ---------------------------------------------------------------------------
// Scratch (static __device__ arrays; no allocations allowed)
// ---------------------------------------------------------------------------
__device__ float g_H[4][(size_t)NMAX * EMB];   // h_list[0..3]
__device__ float g_AGG[(size_t)NMAX * EMB];    // pass-A aggregated output (fp32)
__device__ float g_H1[(size_t)NMAX * ENC1];    // encoder intermediate
__device__ __half2 g_YA[(size_t)NMAX * 64];    // fp16 messages, pass A
__device__ __half2 g_YB[(size_t)NMAX * 64];    // fp16 messages, pass B
__device__ __half2 g_IN[(size_t)NMAX * 64];    // fp16 init (self term), reused A/B
__device__ float g_disA[NMAX];
__device__ float g_disB[NMAX];
__device__ float g_invA[NMAX];
__device__ float g_invB[NMAX];
// CSR scratch: [0,N) rowcntA | [N,2N) rowcntB | [2N,4N) colcnt (A then B)
//              [4N,6N) cursors (A then B)
__device__ int g_icsr[6 * NMAX];
__device__ int g_offs[2 * NMAX];
__device__ int g_src[2 * EMAX];
__device__ int g_bsums[512];
// Prepped weight chunks: 18 chunks of [128 n x 64 k] bf16, XOR-swizzled, hi/lo.
__device__ __nv_bfloat16 g_Bhi[18 * 8192];
__device__ __nv_bfloat16 g_Blo[18 * 8192];

// ---------------------------------------------------------------------------
// Helpers
// ---------------------------------------------------------------------------
__device__ __forceinline__ float leaky(float v) {
    return v >= 0.0f ? v : NEG_SLOPE * v;
}
__device__ __forceinline__ float relu_(float v) { return fmaxf(v, 0.0f); }

__device__ __forceinline__ uint32_t smem_u32(const void* p) {
    uint32_t a;
    asm("{ .reg .u64 t; cvta.to.shared.u64 t, %1; cvt.u32.u64 %0, t; }"
        : "=r"(a) : "l"(p));
    return a;
}

__device__ __forceinline__ void ldsm4(uint32_t* r, uint32_t addr) {
    asm volatile("ldmatrix.sync.aligned.m8n8.x4.shared.b16 {%0,%1,%2,%3}, [%4];"
                 : "=r"(r[0]), "=r"(r[1]), "=r"(r[2]), "=r"(r[3]) : "r"(addr));
}

__device__ __forceinline__ void mma16816(float* c, const uint32_t* a,
                                         uint32_t b0, uint32_t b1) {
    asm volatile(
        "mma.sync.aligned.m16n8k16.row.col.f32.bf16.bf16.f32 "
        "{%0,%1,%2,%3}, {%4,%5,%6,%7}, {%8,%9}, {%0,%1,%2,%3};"
        : "+f"(c[0]), "+f"(c[1]), "+f"(c[2]), "+f"(c[3])
        : "r"(a[0]), "r"(a[1]), "r"(a[2]), "r"(a[3]), "r"(b0), "r"(b1));
}

__device__ __forceinline__ void cp_async16(uint32_t smaddr, const void* g,
                                           int srcsize) {
    asm volatile("cp.async.cg.shared.global [%0], [%1], 16, %2;"
                 :: "r"(smaddr), "l"(g), "r"(srcsize));
}
#define CP_COMMIT() asm volatile("cp.async.commit_group;" ::: "memory")
#define CP_WAIT0()  asm volatile("cp.async.wait_group 0;" ::: "memory")

// fp32x4 -> swizzled bf16 hi/lo store (packed converts)
__device__ __forceinline__ void store_hilo(char* smbase, int off, float4 v) {
    __nv_bfloat162 h01 = __float22bfloat162_rn(make_float2(v.x, v.y));
    __nv_bfloat162 h23 = __float22bfloat162_rn(make_float2(v.z, v.w));
    float2 hf01 = __bfloat1622float2(h01);
    float2 hf23 = __bfloat1622float2(h23);
    __nv_bfloat162 l01 = __float22bfloat162_rn(make_float2(v.x - hf01.x, v.y - hf01.y));
    __nv_bfloat162 l23 = __float22bfloat162_rn(make_float2(v.z - hf23.x, v.w - hf23.y));
    uint2 hi = make_uint2(*reinterpret_cast<uint32_t*>(&h01),
                          *reinterpret_cast<uint32_t*>(&h23));
    uint2 lo = make_uint2(*reinterpret_cast<uint32_t*>(&l01),
                          *reinterpret_cast<uint32_t*>(&l23));
    *(uint2*)(smbase + 0     + off) = hi;   // SM_A_HI == 0
    *(uint2*)(smbase + 16384 + off) = lo;   // SM_A_LO == 16384
}

// ---------------------------------------------------------------------------
// CSR build kernels
// ---------------------------------------------------------------------------
__global__ void zero_kernel(int* p, int n) {
    int i = blockIdx.x * blockDim.x + threadIdx.x;
    if (i < n) p[i] = 0;
}

__global__ void hist2_kernel(const int* __restrict__ rows,
                             const int* __restrict__ cols,
                             int* __restrict__ rowcnt,
                             int* __restrict__ colcnt, int E) {
    int e = blockIdx.x * blockDim.x + threadIdx.x;
    if (e >= E) return;
    atomicAdd(&rowcnt[rows[e]], 1);
    atomicAdd(&colcnt[cols[e]], 1);
}

__global__ void deg_fin_kernel(const int* __restrict__ cnt,
                               float* __restrict__ dis,
                               float* __restrict__ inv, int n) {
    int i = blockIdx.x * blockDim.x + threadIdx.x;
    if (i < n) {
        float d = (float)(cnt[i] + 1);
        dis[i] = rsqrtf(d);
        inv[i] = 1.0f / d;
    }
}

__global__ void scan_block_kernel(const int* __restrict__ in, int* __restrict__ out,
                                  int* __restrict__ bsums, int n) {
    __shared__ int sh[256];
    const int base = blockIdx.x * 1024;
    const int t = threadIdx.x;
    int v[4]; int s = 0;
#pragma unroll
    for (int j = 0; j < 4; j++) {
        int i = base + t * 4 + j;
        v[j] = (i < n) ? in[i] : 0;
        s += v[j];
    }
    sh[t] = s;
    __syncthreads();
    for (int off = 1; off < 256; off <<= 1) {
        int x = (t >= off) ? sh[t - off] : 0;
        __syncthreads();
        sh[t] += x;
        __syncthreads();
    }
    int run = (t > 0) ? sh[t - 1] : 0;
    if (t == 255) bsums[blockIdx.x] = sh[255];
#pragma unroll
    for (int j = 0; j < 4; j++) {
        int i = base + t * 4 + j;
        if (i < n) out[i] = run;
        run += v[j];
    }
}

__global__ void scan_sums_kernel(int* bsums, int nb) {
    __shared__ int sh[512];
    int t = threadIdx.x;
    sh[t] = (t < nb) ? bsums[t] : 0;
    __syncthreads();
    for (int off = 1; off < 512; off <<= 1) {
        int x = (t >= off) ? sh[t - off] : 0;
        __syncthreads();
        sh[t] += x;
        __syncthreads();
    }
    if (t < nb) bsums[t] = (t > 0) ? sh[t - 1] : 0;
}

__global__ void scan_add_kernel(int* __restrict__ out, const int* __restrict__ bsums,
                                int n) {
    int i = blockIdx.x * blockDim.x + threadIdx.x;
    if (i < n) out[i] += bsums[i >> 10];
}

__global__ void fill_kernel(const int* __restrict__ rows, const int* __restrict__ cols,
                            const int* __restrict__ offs, int* __restrict__ cursor,
                            int* __restrict__ src, int E, int obase) {
    int e = blockIdx.x * blockDim.x + threadIdx.x;
    if (e >= E) return;
    int c = cols[e];
    int pos = offs[obase + c] + atomicAdd(&cursor[obase + c], 1);
    src[pos] = rows[e];
}

// ---------------------------------------------------------------------------
// Merged weight prep: 18 chunks of [128n x 64k], swizzled bf16 hi/lo
// ---------------------------------------------------------------------------
__global__ void prep_all_kernel(const float* __restrict__ enc_w1,
                                const float* __restrict__ enc_w2,
                                const float* __restrict__ conv_w,
                                const float* __restrict__ reconv_w,
                                __nv_bfloat16* __restrict__ BH,
                                __nv_bfloat16* __restrict__ BL) {
    const int chunk = blockIdx.x >> 5;
    const int idx = (blockIdx.x & 31) * 256 + threadIdx.x;
    const int n = idx >> 6;
    const int k = idx & 63;
    const float* W; int ldn, k0, n0, kcount;
    if (chunk < 2)      { W = enc_w1; ldn = 256; k0 = 0; n0 = chunk * 128; kcount = 32; }
    else if (chunk < 6) { W = enc_w2; ldn = 128; k0 = (chunk - 2) * 64; n0 = 0; kcount = 64; }
    else if (chunk < 12) {
        int l = (chunk - 6) >> 1, c = (chunk - 6) & 1;
        W = conv_w + (size_t)l * 16384; ldn = 128; k0 = c * 64; n0 = 0; kcount = 64;
    } else {
        int l = (chunk - 12) >> 1, c = (chunk - 12) & 1;
        W = reconv_w + (size_t)l * 16384; ldn = 128; k0 = c * 64; n0 = 0; kcount = 64;
    }
    float v = (k < kcount) ? W[(size_t)(k0 + k) * ldn + n0 + n] : 0.0f;
    __nv_bfloat16 h = __float2bfloat16(v);
    __nv_bfloat16 l = __float2bfloat16(v - __bfloat162float(h));
    int off = n * 128 + ((k * 2) ^ ((n & 7) << 4));
    BH[(size_t)chunk * 8192 + (off >> 1)] = h;
    BL[(size_t)chunk * 8192 + (off >> 1)] = l;
}

// ---------------------------------------------------------------------------
// Tensor-core GEMM (mma.sync bf16 3-split) with cp.async A pipeline.
//  mode 0: out[gr*ostride+colofs+n] = act? leaky(d) : d
//          if (aux && gr<rows_aux) also aux[gr*512+aofs+n]
//  mode 1 (GCN prep): ibuf[gr][n] = half( relu(d+root[n]) * inv[gr] )  (init)
//                     ybuf[gr][n] = half( dis[gr] * relu(d) )          (message)
//  Optional second half (Bhi2 != null, requires kchunks==1, mode 0).
// ---------------------------------------------------------------------------
#define SM_A_HI 0
#define SM_A_LO 16384
#define SM_B_HI 32768
#define SM_B_LO 49152
#define SM_STAGE 65536
#define SMEM_TC 98304

__global__ void __launch_bounds__(256, 2)
gemm_tc_kernel(const float* __restrict__ A, int lda, int M,
               const __nv_bfloat16* __restrict__ BhiG,
               const __nv_bfloat16* __restrict__ BloG,
               int kchunks, int KV,
               const float* __restrict__ bias,
               float* __restrict__ out, int ostride, int colofs, int act,
               float* __restrict__ aux, int aofs, int rows_aux,
               int mode,
               const float* __restrict__ root,
               const float* __restrict__ dis,
               const float* __restrict__ inv,
               __half2* __restrict__ ybuf,
               __half2* __restrict__ ibuf,
               const __nv_bfloat16* __restrict__ Bhi2,
               const __nv_bfloat16* __restrict__ Blo2,
               const float* __restrict__ bias2, int colofs2) {
    extern __shared__ char sm[];
    const uint32_t sb = smem_u32(sm);
    const int tid = threadIdx.x;
    const int w = tid >> 5;
    const int lane = tid & 31;
    const int wm = w & 3;
    const int wn = w >> 2;
    const int row0 = blockIdx.x * 128;
    const int nhalves = Bhi2 ? 2 : 1;

    // ---- prefetch A chunk 0 via cp.async ----
    {
        const int kcols0 = (KV < 64) ? KV : 64;
#pragma unroll
        for (int i = 0; i < 8; i++) {
            const int idx = tid + i * 256;
            const int r = idx >> 4;
            const int c4 = idx & 15;
            const int gr = row0 + r;
            const bool valid = (gr < M) && (c4 * 4 < kcols0);
            const float* gsrc = valid ? (A + (size_t)gr * lda + c4 * 4) : A;
            cp_async16(sb + SM_STAGE + idx * 16, gsrc, valid ? 16 : 0);
        }
        CP_COMMIT();
    }

    for (int half = 0; half < nhalves; half++) {
        const __nv_bfloat16* BhiH = half ? Bhi2 : BhiG;
        const __nv_bfloat16* BloH = half ? Blo2 : BloG;
        const float* biasH = half ? bias2 : bias;
        const int colofsH = half ? colofs2 : colofs;

        float acc[2][8][4];
#pragma unroll
        for (int a = 0; a < 2; a++)
#pragma unroll
            for (int b = 0; b < 8; b++)
#pragma unroll
                for (int c = 0; c < 4; c++) acc[a][b][c] = 0.0f;

        for (int ck = 0; ck < kchunks; ck++) {
            int kcols = KV - ck * 64; if (kcols > 64) kcols = 64;
            const int ksteps = (kcols + 15) >> 4;

            if (half > 0) __syncthreads();   // protect B buffer reuse

            // ---- stage B chunk ----
            {
                const float4* shg = (const float4*)(BhiH + (size_t)ck * 8192);
                const float4* slg = (const float4*)(BloH + (size_t)ck * 8192);
                float4* dh = (float4*)(sm + SM_B_HI);
                float4* dl = (float4*)(sm + SM_B_LO);
                for (int i = tid; i < 1024; i += 256) { dh[i] = shg[i]; dl[i] = slg[i]; }
            }

            // ---- A chunk: wait cp.async, convert from SMEM stage (half 0) ----
            if (half == 0) {
                CP_WAIT0();
                // each thread reads exactly the stage entries it wrote: no barrier
#pragma unroll
                for (int i = 0; i < 8; i++) {
                    const int idx = tid + i * 256;
                    const int r = idx >> 4;
                    const int c4 = idx & 15;
                    float4 v = *(const float4*)(sm + SM_STAGE + idx * 16);
                    int off = r * 128 + ((c4 * 8) ^ ((r & 7) << 4));
                    store_hilo(sm, off, v);
                }
                // ---- prefetch next A chunk (overlaps with compute below) ----
                if (ck + 1 < kchunks) {
                    const int kbase2 = (ck + 1) * 64;
                    int kcols2 = KV - kbase2; if (kcols2 > 64) kcols2 = 64;
#pragma unroll
                    for (int i = 0; i < 8; i++) {
                        const int idx = tid + i * 256;
                        const int r = idx >> 4;
                        const int c4 = idx & 15;
                        const int gr = row0 + r;
                        const bool valid = (gr < M) && (c4 * 4 < kcols2);
                        const float* gsrc = valid
                            ? (A + (size_t)gr * lda + kbase2 + c4 * 4) : A;
                        cp_async16(sb + SM_STAGE + idx * 16, gsrc, valid ? 16 : 0);
                    }
                    CP_COMMIT();
                }
            }
            __syncthreads();

            // ---- compute ----
            for (int ks = 0; ks < ksteps; ks++) {
                uint32_t ah[2][4], al[2][4];
                {
                    const int rr = (lane & 15);
                    const int colb = ks * 32 + (lane & 16);
#pragma unroll
                    for (int mt = 0; mt < 2; mt++) {
                        const int row = wm * 32 + mt * 16 + rr;
                        const uint32_t ad = (uint32_t)(row * 128 +
                                           (colb ^ ((row & 7) << 4)));
                        ldsm4(ah[mt], sb + SM_A_HI + ad);
                        ldsm4(al[mt], sb + SM_A_LO + ad);
                    }
                }
#pragma unroll
                for (int np = 0; np < 4; np++) {
                    const int nb = wn * 64 + np * 16;
                    const int n = nb + (lane & 7) + ((lane & 16) >> 1);
                    const int colb = ks * 32 + ((lane & 8) << 1);
                    const uint32_t bd = (uint32_t)(n * 128 + (colb ^ ((n & 7) << 4)));
                    uint32_t bh[4], bl[4];
                    ldsm4(bh, sb + SM_B_HI + bd);
                    ldsm4(bl, sb + SM_B_LO + bd);
#pragma unroll
                    for (int mt = 0; mt < 2; mt++) {
#pragma unroll
                        for (int nt = 0; nt < 2; nt++) {
                            float* c = acc[mt][np * 2 + nt];
                            mma16816(c, ah[mt], bh[nt * 2], bh[nt * 2 + 1]);
                            mma16816(c, ah[mt], bl[nt * 2], bl[nt * 2 + 1]);
                            mma16816(c, al[mt], bh[nt * 2], bh[nt * 2 + 1]);
                        }
                    }
                }
            }
            __syncthreads();
        }

        // ---- epilogue ----
        const int quad = lane >> 2;
        const int tq = lane & 3;
#pragma unroll
        for (int mt = 0; mt < 2; mt++) {
#pragma unroll
            for (int half8 = 0; half8 < 2; half8++) {
                const int gr = row0 + wm * 32 + mt * 16 + half8 * 8 + quad;
                if (gr >= M) continue;
                if (mode == 0) {
                    float* po = out + (size_t)gr * ostride + colofsH + wn * 64;
                    float* pa = (aux && gr < rows_aux)
                              ? aux + (size_t)gr * 512 + aofs + wn * 64 : nullptr;
#pragma unroll
                    for (int j = 0; j < 8; j++) {
                        const int col = j * 8 + tq * 2;
                        float c0 = acc[mt][j][half8 * 2 + 0] + __ldg(biasH + wn * 64 + col);
                        float c1 = acc[mt][j][half8 * 2 + 1] + __ldg(biasH + wn * 64 + col + 1);
                        float2 o;
                        o.x = act ? leaky(c0) : c0;
                        o.y = act ? leaky(c1) : c1;
                        *(float2*)(po + col) = o;
                        if (pa) *(float2*)(pa + col) = o;
                    }
                } else {
                    const float id = __ldg(inv + gr);
                    const float dg = __ldg(dis + gr);
                    __half2* pi = ibuf + (size_t)gr * 64 + wn * 32;
                    __half2* py = ybuf + (size_t)gr * 64 + wn * 32;
#pragma unroll
                    for (int j = 0; j < 8; j++) {
                        const int col = j * 8 + tq * 2;
                        float xl0 = acc[mt][j][half8 * 2 + 0] + __ldg(bias + wn * 64 + col);
                        float xl1 = acc[mt][j][half8 * 2 + 1] + __ldg(bias + wn * 64 + col + 1);
                        pi[col >> 1] = __floats2half2_rn(
                            relu_(xl0 + __ldg(root + wn * 64 + col)) * id,
                            relu_(xl1 + __ldg(root + wn * 64 + col + 1)) * id);
                        py[col >> 1] = __floats2half2_rn(dg * relu_(xl0), dg * relu_(xl1));
                    }
                }
            }
        }
    }
}

// ---------------------------------------------------------------------------
// CSR gather helpers (R12 version — empirically best at avg degree ~3)
// ---------------------------------------------------------------------------
__device__ __forceinline__ float4 gather_sum(const __half2* __restrict__ y,
                                             const int* __restrict__ src,
                                             int o, int k, int lane) {
    float4 na = make_float4(0.f, 0.f, 0.f, 0.f);
    int j = 0;
    for (; j + 2 <= k; j += 2) {
        const int s0 = __ldg(src + o + j);
        const int s1 = __ldg(src + o + j + 1);
        const uint2 v0 = *(const uint2*)(y + (size_t)s0 * 64 + lane * 2);
        const uint2 v1 = *(const uint2*)(y + (size_t)s1 * 64 + lane * 2);
        float2 a0 = __half22float2(*(const __half2*)&v0.x);
        float2 a1 = __half22float2(*(const __half2*)&v0.y);
        float2 b0 = __half22float2(*(const __half2*)&v1.x);
        float2 b1 = __half22float2(*(const __half2*)&v1.y);
        na.x += a0.x + b0.x;
        na.y += a0.y + b0.y;
        na.z += a1.x + b1.x;
        na.w += a1.y + b1.y;
    }
    if (j < k) {
        const int s0 = __ldg(src + o + j);
        const uint2 v0 = *(const uint2*)(y + (size_t)s0 * 64 + lane * 2);
        float2 a0 = __half22float2(*(const __half2*)&v0.x);
        float2 a1 = __half22float2(*(const __half2*)&v0.y);
        na.x += a0.x; na.y += a0.y; na.z += a1.x; na.w += a1.y;
    }
    return na;
}

__device__ __forceinline__ float4 load_init_h(const __half2* __restrict__ ibuf,
                                              int c, int lane) {
    const uint2 iv = *(const uint2*)(ibuf + (size_t)c * 64 + lane * 2);
    float2 i0 = __half22float2(*(const __half2*)&iv.x);
    float2 i1 = __half22float2(*(const __half2*)&iv.y);
    return make_float4(i0.x, i0.y, i1.x, i1.y);
}

// ---------------------------------------------------------------------------
// Pass-A aggregation: agg[c] = init[c] + dis[c] * sum YA[src]   (fp32 out)
// ---------------------------------------------------------------------------
__global__ void agg_kernel(const __half2* __restrict__ ibuf,
                           const __half2* __restrict__ y,
                           const int* __restrict__ offs,
                           const int* __restrict__ cnt,
                           const int* __restrict__ src,
                           const float* __restrict__ dis,
                           float* __restrict__ agg, int Nn, int obase) {
    const int c = blockIdx.x * 8 + (threadIdx.x >> 5);
    if (c >= Nn) return;
    const int lane = threadIdx.x & 31;

    float4 acc = load_init_h(ibuf, c, lane);
    const int o = __ldg(offs + obase + c);
    const int k = __ldg(cnt + obase + c);
    const float dc = __ldg(dis + c);
    float4 na = gather_sum(y, src, o, k, lane);
    acc.x += dc * na.x; acc.y += dc * na.y;
    acc.z += dc * na.z; acc.w += dc * na.w;
    ((float4*)agg)[(size_t)c * 32 + lane] = acc;
}

// ---------------------------------------------------------------------------
// Pass-B aggregation + LayerNorm + LeakyReLU + residual.
// ---------------------------------------------------------------------------
__global__ void agg_ln_kernel(const __half2* __restrict__ ibuf,
                              const __half2* __restrict__ y,
                              const int* __restrict__ offs,
                              const int* __restrict__ cnt,
                              const int* __restrict__ src,
                              const float* __restrict__ dis,
                              const float* __restrict__ g,
                              const float* __restrict__ b,
                              const float* __restrict__ hprev,
                              float* __restrict__ hnext, int hstride, int hofs,
                              float* __restrict__ aux, int aofs, int rows_aux,
                              int Nn, int obase) {
    const int c = blockIdx.x * 8 + (threadIdx.x >> 5);
    if (c >= Nn) return;
    const int lane = threadIdx.x & 31;

    float4 acc = load_init_h(ibuf, c, lane);
    const int o = __ldg(offs + obase + c);
    const int k = __ldg(cnt + obase + c);
    const float dc = __ldg(dis + c);
    float4 na = gather_sum(y, src, o, k, lane);
    acc.x += dc * na.x; acc.y += dc * na.y;
    acc.z += dc * na.z; acc.w += dc * na.w;

    float s1 = acc.x + acc.y + acc.z + acc.w;
#pragma unroll
    for (int off = 16; off > 0; off >>= 1) s1 += __shfl_xor_sync(0xffffffffu, s1, off);
    const float mu = s1 * (1.0f / 128.0f);
    float dx = acc.x - mu, dy = acc.y - mu, dz = acc.z - mu, dw = acc.w - mu;
    float q = dx * dx + dy * dy + dz * dz + dw * dw;
#pragma unroll
    for (int off = 16; off > 0; off >>= 1) q += __shfl_xor_sync(0xffffffffu, q, off);
    const float rstd = rsqrtf(q * (1.0f / 128.0f) + LN_EPS);

    float4 gg = ((const float4*)g)[lane];
    float4 bb = ((const float4*)b)[lane];
    float4 hp = ((const float4*)hprev)[(size_t)c * 32 + lane];
    float4 out;
    out.x = leaky(dx * rstd * gg.x + bb.x) + hp.x;
    out.y = leaky(dy * rstd * gg.y + bb.y) + hp.y;
    out.z = leaky(dz * rstd * gg.z + bb.z) + hp.z;
    out.w = leaky(dw * rstd * gg.w + bb.w) + hp.w;
    ((float4*)(hnext + (size_t)c * hstride + hofs))[lane] = out;
    if (aux && c < rows_aux)
        ((float4*)(aux + (size_t)c * 512 + aofs))[lane] = out;
}

// ---------------------------------------------------------------------------
// Launch
// ---------------------------------------------------------------------------
extern "C" void kernel_launch(void* const* d_in, const int* in_sizes, int n_in,
                              void* d_out, int out_size) {
    const float* x        = (const float*)d_in[0];
    const float* enc_w1   = (const float*)d_in[1];
    const float* enc_b1   = (const float*)d_in[2];
    const float* enc_w2   = (const float*)d_in[3];
    const float* enc_b2   = (const float*)d_in[4];
    const float* conv_w   = (const float*)d_in[5];
    const float* conv_b   = (const float*)d_in[6];
    const float* conv_rt  = (const float*)d_in[7];
    const float* reconv_w = (const float*)d_in[8];
    const float* reconv_b = (const float*)d_in[9];
    const float* reconv_rt= (const float*)d_in[10];
    const float* ln_g     = (const float*)d_in[11];
    const float* ln_b     = (const float*)d_in[12];
    const int*   eA       = (const int*)d_in[13];
    const int*   eB       = (const int*)d_in[14];

    const int N  = in_sizes[0] / 32;
    const int Ea = in_sizes[13] / 2;
    const int Eb = in_sizes[14] / 2;
    const int rows_out = out_size / 512;

    const int* rowsA = eA; const int* colsA = eA + Ea;
    const int* rowsB = eB; const int* colsB = eB + Eb;

    void* p;
    cudaGetSymbolAddress(&p, g_H);    float* H    = (float*)p;
    cudaGetSymbolAddress(&p, g_AGG);  float* AGG  = (float*)p;
    cudaGetSymbolAddress(&p, g_H1);   float* H1E  = (float*)p;
    cudaGetSymbolAddress(&p, g_YA);   __half2* YA = (__half2*)p;
    cudaGetSymbolAddress(&p, g_YB);   __half2* YB = (__half2*)p;
    cudaGetSymbolAddress(&p, g_IN);   __half2* IN = (__half2*)p;
    cudaGetSymbolAddress(&p, g_disA); float* disA = (float*)p;
    cudaGetSymbolAddress(&p, g_disB); float* disB = (float*)p;
    cudaGetSymbolAddress(&p, g_invA); float* invA = (float*)p;
    cudaGetSymbolAddress(&p, g_invB); float* invB = (float*)p;
    cudaGetSymbolAddress(&p, g_icsr); int* icsr   = (int*)p;
    cudaGetSymbolAddress(&p, g_offs); int* offs   = (int*)p;
    cudaGetSymbolAddress(&p, g_src);  int* src    = (int*)p;
    cudaGetSymbolAddress(&p, g_bsums);int* bsums  = (int*)p;
    cudaGetSymbolAddress(&p, g_Bhi);  __nv_bfloat16* BH = (__nv_bfloat16*)p;
    cudaGetSymbolAddress(&p, g_Blo);  __nv_bfloat16* BL = (__nv_bfloat16*)p;

    int* rowcntA = icsr;
    int* rowcntB = icsr + NMAX;
    int* colcnt  = icsr + 2 * NMAX;
    int* cursor  = icsr + 4 * NMAX;

    const size_t hstride = (size_t)NMAX * EMB;
    float* dout = (float*)d_out;

    cudaFuncSetAttribute(gemm_tc_kernel,
                         cudaFuncAttributeMaxDynamicSharedMemorySize, SMEM_TC);

    // ---- side stream for the CSR build (overlaps with encoder GEMMs) ----
    static cudaStream_t s2 = nullptr;
    static cudaEvent_t ev_fork = nullptr, ev_join = nullptr;
    if (!s2) {
        cudaStreamCreateWithFlags(&s2, cudaStreamNonBlocking);
        cudaEventCreateWithFlags(&ev_fork, cudaEventDisableTiming);
        cudaEventCreateWithFlags(&ev_join, cudaEventDisableTiming);
    }

    cudaEventRecord(ev_fork, 0);
    cudaStreamWaitEvent(s2, ev_fork, 0);

    // ---- CSR build + degrees (side stream) ----
    zero_kernel<<<(6 * NMAX + 255) / 256, 256, 0, s2>>>(icsr, 6 * NMAX);
    hist2_kernel<<<(Ea + 255) / 256, 256, 0, s2>>>(rowsA, colsA, rowcntA, colcnt, Ea);
    hist2_kernel<<<(Eb + 255) / 256, 256, 0, s2>>>(rowsB, colsB, rowcntB,
                                                   colcnt + NMAX, Eb);
    deg_fin_kernel<<<(N + 255) / 256, 256, 0, s2>>>(rowcntA, disA, invA, N);
    deg_fin_kernel<<<(N + 255) / 256, 256, 0, s2>>>(rowcntB, disB, invB, N);
    {
        const int n2 = 2 * NMAX;
        const int nb = (n2 + 1023) / 1024;
        scan_block_kernel<<<nb, 256, 0, s2>>>(colcnt, offs, bsums, n2);
        scan_sums_kernel<<<1, 512, 0, s2>>>(bsums, nb);
        scan_add_kernel<<<(n2 + 255) / 256, 256, 0, s2>>>(offs, bsums, n2);
    }
    fill_kernel<<<(Ea + 255) / 256, 256, 0, s2>>>(rowsA, colsA, offs, cursor, src,
                                                  Ea, 0);
    fill_kernel<<<(Eb + 255) / 256, 256, 0, s2>>>(rowsB, colsB, offs, cursor, src,
                                                  Eb, NMAX);
    cudaEventRecord(ev_join, s2);

    // ---- weight prep + encoder (main stream, concurrent with CSR build) ----
    prep_all_kernel<<<18 * 32, 256>>>(enc_w1, enc_w2, conv_w, reconv_w, BH, BL);

    const int tiles = (N + 127) / 128;

    // enc1: single launch covering both N-halves (A tile staged once)
    gemm_tc_kernel<<<tiles, 256, SMEM_TC>>>(x, 32, N,
        BH + 0 * 8192, BL + 0 * 8192, 1, 32, enc_b1, H1E, 256, 0, 1,
        nullptr, 0, 0, 0, nullptr, nullptr, nullptr, nullptr, nullptr,
        BH + 1 * 8192, BL + 1 * 8192, enc_b1 + 128, 128);
    // enc2 -> H0 + JK slice 0 of d_out
    gemm_tc_kernel<<<tiles, 256, SMEM_TC>>>(H1E, 256, N,
        BH + 2 * 8192, BL + 2 * 8192, 4, 256, enc_b2, H, 128, 0, 1,
        dout, 0, rows_out, 0, nullptr, nullptr, nullptr, nullptr, nullptr,
        nullptr, nullptr, nullptr, 0);

    // join: GCN layers need the CSR
    cudaStreamWaitEvent(0, ev_join, 0);

    // ---- GCN layers ----
    for (int l = 0; l < 3; l++) {
        const float* hl = H + (size_t)l * hstride;
        float* hn = H + (size_t)(l + 1) * hstride;
        const int last = (l == 2);

        // conv (edge set A): GEMM -> IN (half init) + YA
        gemm_tc_kernel<<<tiles, 256, SMEM_TC>>>(hl, 128, N,
            BH + (6 + 2 * l) * 8192, BL + (6 + 2 * l) * 8192, 2, 128,
            conv_b + l * EMB, nullptr, 0, 0, 0,
            nullptr, 0, 0, 1, conv_rt + l * EMB, disA, invA, YA, IN,
            nullptr, nullptr, nullptr, 0);
        agg_kernel<<<(N + 7) / 8, 256>>>(IN, YA, offs, colcnt, src, disA, AGG, N, 0);

        // reconv (edge set B): GEMM reads AGG -> IN (half init, reused) + YB
        gemm_tc_kernel<<<tiles, 256, SMEM_TC>>>(AGG, 128, N,
            BH + (12 + 2 * l) * 8192, BL + (12 + 2 * l) * 8192, 2, 128,
            reconv_b + l * EMB, nullptr, 0, 0, 0,
            nullptr, 0, 0, 1, reconv_rt + l * EMB, disB, invB, YB, IN,
            nullptr, nullptr, nullptr, 0);

        if (!last) {
            agg_ln_kernel<<<(N + 7) / 8, 256>>>(IN, YB, offs, colcnt, src, disB,
                ln_g + l * EMB, ln_b + l * EMB, hl,
                hn, 128, 0, dout, (l + 1) * 128, rows_out, N, NMAX);
        } else {
            agg_ln_kernel<<<(rows_out + 7) / 8, 256>>>(IN, YB, offs, colcnt, src, disB,
                ln_g + l * EMB, ln_b + l * EMB, hl,
                dout, 512, 384, nullptr, 0, 0, rows_out, NMAX);
        }
    }
}

// round 16
// speedup vs baseline: 1.3554x; 1.1558x over previous
#include <cuda_runtime.h>
#include <cuda_bf16.h>
#include <cuda_fp16.h>
#include <cstddef>
#include <cstdint>

// ---------------------------------------------------------------------------
// Problem constants
// ---------------------------------------------------------------------------
#define NMAX   200000
#define EMAX   650000
#define EMB    128
#define ENC1   256
#define NEG_SLOPE 0.1f
#define LN_EPS 1e-5f

// ---------------------------------------------------------------------------
// Scratch (static __device__ arrays; no allocations allowed)
// ---------------------------------------------------------------------------
__device__ float g_H[4][(size_t)NMAX * EMB];   // h_list[0..3]
__device__ float g_AGG[(size_t)NMAX * EMB];    // pass-A aggregated output (fp32)
__device__ float g_H1[(size_t)NMAX * ENC1];    // encoder intermediate
__device__ __half2 g_YA[(size_t)NMAX * 64];    // fp16 messages, pass A
__device__ __half2 g_YB[(size_t)NMAX * 64];    // fp16 messages, pass B
__device__ __half2 g_IN[(size_t)NMAX * 64];    // fp16 init (self term), reused A/B
__device__ float g_disA[NMAX];
__device__ float g_disB[NMAX];
__device__ float g_invA[NMAX];
__device__ float g_invB[NMAX];
// CSR scratch: [0,N) rowcntA | [N,2N) rowcntB | [2N,4N) colcnt (A then B)
//              [4N,6N) cursors (A then B)
__device__ int g_icsr[6 * NMAX];
__device__ int g_offs[2 * NMAX];
__device__ int g_src[2 * EMAX];
__device__ int g_bsums[512];
// Prepped weight chunks: 18 chunks of [128 n x 64 k] fp16, XOR-swizzled.
__device__ __half g_W16[18 * 8192];

// ---------------------------------------------------------------------------
// Helpers
// ---------------------------------------------------------------------------
__device__ __forceinline__ float leaky(float v) {
    return v >= 0.0f ? v : NEG_SLOPE * v;
}
__device__ __forceinline__ float relu_(float v) { return fmaxf(v, 0.0f); }

__device__ __forceinline__ uint32_t smem_u32(const void* p) {
    uint32_t a;
    asm("{ .reg .u64 t; cvta.to.shared.u64 t, %1; cvt.u32.u64 %0, t; }"
        : "=r"(a) : "l"(p));
    return a;
}

__device__ __forceinline__ void ldsm4(uint32_t* r, uint32_t addr) {
    asm volatile("ldmatrix.sync.aligned.m8n8.x4.shared.b16 {%0,%1,%2,%3}, [%4];"
                 : "=r"(r[0]), "=r"(r[1]), "=r"(r[2]), "=r"(r[3]) : "r"(addr));
}

// fp16 tensor-core MMA, fp32 accumulate
__device__ __forceinline__ void mma16816h(float* c, const uint32_t* a,
                                          uint32_t b0, uint32_t b1) {
    asm volatile(
        "mma.sync.aligned.m16n8k16.row.col.f32.f16.f16.f32 "
        "{%0,%1,%2,%3}, {%4,%5,%6,%7}, {%8,%9}, {%0,%1,%2,%3};"
        : "+f"(c[0]), "+f"(c[1]), "+f"(c[2]), "+f"(c[3])
        : "r"(a[0]), "r"(a[1]), "r"(a[2]), "r"(a[3]), "r"(b0), "r"(b1));
}

__device__ __forceinline__ void cp_async16(uint32_t smaddr, const void* g,
                                           int srcsize) {
    asm volatile("cp.async.cg.shared.global [%0], [%1], 16, %2;"
                 :: "r"(smaddr), "l"(g), "r"(srcsize));
}
#define CP_COMMIT() asm volatile("cp.async.commit_group;" ::: "memory")
#define CP_WAIT0()  asm volatile("cp.async.wait_group 0;" ::: "memory")

// fp32x4 -> swizzled fp16x4 store
__device__ __forceinline__ void store_h16(char* smbase, int off, float4 v) {
    __half2 h01 = __floats2half2_rn(v.x, v.y);
    __half2 h23 = __floats2half2_rn(v.z, v.w);
    *(uint2*)(smbase + off) = make_uint2(*reinterpret_cast<uint32_t*>(&h01),
                                         *reinterpret_cast<uint32_t*>(&h23));
}

// ---------------------------------------------------------------------------
// CSR build kernels
// ---------------------------------------------------------------------------
__global__ void zero_kernel(int* p, int n) {
    int i = blockIdx.x * blockDim.x + threadIdx.x;
    if (i < n) p[i] = 0;
}

__global__ void hist2_kernel(const int* __restrict__ rows,
                             const int* __restrict__ cols,
                             int* __restrict__ rowcnt,
                             int* __restrict__ colcnt, int E) {
    int e = blockIdx.x * blockDim.x + threadIdx.x;
    if (e >= E) return;
    atomicAdd(&rowcnt[rows[e]], 1);
    atomicAdd(&colcnt[cols[e]], 1);
}

__global__ void deg_fin_kernel(const int* __restrict__ cnt,
                               float* __restrict__ dis,
                               float* __restrict__ inv, int n) {
    int i = blockIdx.x * blockDim.x + threadIdx.x;
    if (i < n) {
        float d = (float)(cnt[i] + 1);
        dis[i] = rsqrtf(d);
        inv[i] = 1.0f / d;
    }
}

__global__ void scan_block_kernel(const int* __restrict__ in, int* __restrict__ out,
                                  int* __restrict__ bsums, int n) {
    __shared__ int sh[256];
    const int base = blockIdx.x * 1024;
    const int t = threadIdx.x;
    int v[4]; int s = 0;
#pragma unroll
    for (int j = 0; j < 4; j++) {
        int i = base + t * 4 + j;
        v[j] = (i < n) ? in[i] : 0;
        s += v[j];
    }
    sh[t] = s;
    __syncthreads();
    for (int off = 1; off < 256; off <<= 1) {
        int x = (t >= off) ? sh[t - off] : 0;
        __syncthreads();
        sh[t] += x;
        __syncthreads();
    }
    int run = (t > 0) ? sh[t - 1] : 0;
    if (t == 255) bsums[blockIdx.x] = sh[255];
#pragma unroll
    for (int j = 0; j < 4; j++) {
        int i = base + t * 4 + j;
        if (i < n) out[i] = run;
        run += v[j];
    }
}

__global__ void scan_sums_kernel(int* bsums, int nb) {
    __shared__ int sh[512];
    int t = threadIdx.x;
    sh[t] = (t < nb) ? bsums[t] : 0;
    __syncthreads();
    for (int off = 1; off < 512; off <<= 1) {
        int x = (t >= off) ? sh[t - off] : 0;
        __syncthreads();
        sh[t] += x;
        __syncthreads();
    }
    if (t < nb) bsums[t] = (t > 0) ? sh[t - 1] : 0;
}

__global__ void scan_add_kernel(int* __restrict__ out, const int* __restrict__ bsums,
                                int n) {
    int i = blockIdx.x * blockDim.x + threadIdx.x;
    if (i < n) out[i] += bsums[i >> 10];
}

__global__ void fill_kernel(const int* __restrict__ rows, const int* __restrict__ cols,
                            const int* __restrict__ offs, int* __restrict__ cursor,
                            int* __restrict__ src, int E, int obase) {
    int e = blockIdx.x * blockDim.x + threadIdx.x;
    if (e >= E) return;
    int c = cols[e];
    int pos = offs[obase + c] + atomicAdd(&cursor[obase + c], 1);
    src[pos] = rows[e];
}

// ---------------------------------------------------------------------------
// Merged weight prep: 18 chunks of [128n x 64k], swizzled fp16
// ---------------------------------------------------------------------------
__global__ void prep_all_kernel(const float* __restrict__ enc_w1,
                                const float* __restrict__ enc_w2,
                                const float* __restrict__ conv_w,
                                const float* __restrict__ reconv_w,
                                __half* __restrict__ W16) {
    const int chunk = blockIdx.x >> 5;
    const int idx = (blockIdx.x & 31) * 256 + threadIdx.x;
    const int n = idx >> 6;
    const int k = idx & 63;
    const float* W; int ldn, k0, n0, kcount;
    if (chunk < 2)      { W = enc_w1; ldn = 256; k0 = 0; n0 = chunk * 128; kcount = 32; }
    else if (chunk < 6) { W = enc_w2; ldn = 128; k0 = (chunk - 2) * 64; n0 = 0; kcount = 64; }
    else if (chunk < 12) {
        int l = (chunk - 6) >> 1, c = (chunk - 6) & 1;
        W = conv_w + (size_t)l * 16384; ldn = 128; k0 = c * 64; n0 = 0; kcount = 64;
    } else {
        int l = (chunk - 12) >> 1, c = (chunk - 12) & 1;
        W = reconv_w + (size_t)l * 16384; ldn = 128; k0 = c * 64; n0 = 0; kcount = 64;
    }
    float v = (k < kcount) ? W[(size_t)(k0 + k) * ldn + n0 + n] : 0.0f;
    int off = n * 128 + ((k * 2) ^ ((n & 7) << 4));
    W16[(size_t)chunk * 8192 + (off >> 1)] = __float2half_rn(v);
}

// ---------------------------------------------------------------------------
// Tensor-core GEMM (mma.sync fp16, fp32 accum) with cp.async A pipeline.
//  mode 0: out[gr*ostride+colofs+n] = act? leaky(d) : d
//          if (aux && gr<rows_aux) also aux[gr*512+aofs+n]
//  mode 1 (GCN prep): ibuf[gr][n] = half( relu(d+root[n]) * inv[gr] )  (init)
//                     ybuf[gr][n] = half( dis[gr] * relu(d) )          (message)
//  Optional second half (W2 != null, requires kchunks==1, mode 0).
// ---------------------------------------------------------------------------
#define SM_A     0
#define SM_B     16384
#define SM_STAGE 32768
#define SMEM_TC  65536

__global__ void __launch_bounds__(256, 2)
gemm_tc_kernel(const float* __restrict__ A, int lda, int M,
               const __half* __restrict__ WG,
               int kchunks, int KV,
               const float* __restrict__ bias,
               float* __restrict__ out, int ostride, int colofs, int act,
               float* __restrict__ aux, int aofs, int rows_aux,
               int mode,
               const float* __restrict__ root,
               const float* __restrict__ dis,
               const float* __restrict__ inv,
               __half2* __restrict__ ybuf,
               __half2* __restrict__ ibuf,
               const __half* __restrict__ W2,
               const float* __restrict__ bias2, int colofs2) {
    extern __shared__ char sm[];
    const uint32_t sb = smem_u32(sm);
    const int tid = threadIdx.x;
    const int w = tid >> 5;
    const int lane = tid & 31;
    const int wm = w & 3;
    const int wn = w >> 2;
    const int row0 = blockIdx.x * 128;
    const int nhalves = W2 ? 2 : 1;

    // ---- prefetch A chunk 0 via cp.async ----
    {
        const int kcols0 = (KV < 64) ? KV : 64;
#pragma unroll
        for (int i = 0; i < 8; i++) {
            const int idx = tid + i * 256;
            const int r = idx >> 4;
            const int c4 = idx & 15;
            const int gr = row0 + r;
            const bool valid = (gr < M) && (c4 * 4 < kcols0);
            const float* gsrc = valid ? (A + (size_t)gr * lda + c4 * 4) : A;
            cp_async16(sb + SM_STAGE + idx * 16, gsrc, valid ? 16 : 0);
        }
        CP_COMMIT();
    }

    for (int half = 0; half < nhalves; half++) {
        const __half* WH = half ? W2 : WG;
        const float* biasH = half ? bias2 : bias;
        const int colofsH = half ? colofs2 : colofs;

        float acc[2][8][4];
#pragma unroll
        for (int a = 0; a < 2; a++)
#pragma unroll
            for (int b = 0; b < 8; b++)
#pragma unroll
                for (int c = 0; c < 4; c++) acc[a][b][c] = 0.0f;

        for (int ck = 0; ck < kchunks; ck++) {
            int kcols = KV - ck * 64; if (kcols > 64) kcols = 64;
            const int ksteps = (kcols + 15) >> 4;

            if (half > 0) __syncthreads();   // protect B buffer reuse

            // ---- stage B chunk (16 KB raw copy) ----
            {
                const float4* shg = (const float4*)(WH + (size_t)ck * 8192);
                float4* dh = (float4*)(sm + SM_B);
                for (int i = tid; i < 1024; i += 256) dh[i] = shg[i];
            }

            // ---- A chunk: wait cp.async, convert from SMEM stage (half 0) ----
            if (half == 0) {
                CP_WAIT0();
                // each thread reads exactly the stage entries it wrote: no barrier
#pragma unroll
                for (int i = 0; i < 8; i++) {
                    const int idx = tid + i * 256;
                    const int r = idx >> 4;
                    const int c4 = idx & 15;
                    float4 v = *(const float4*)(sm + SM_STAGE + idx * 16);
                    int off = r * 128 + ((c4 * 8) ^ ((r & 7) << 4));
                    store_h16(sm + SM_A, off, v);
                }
                // ---- prefetch next A chunk (overlaps with compute below) ----
                if (ck + 1 < kchunks) {
                    const int kbase2 = (ck + 1) * 64;
                    int kcols2 = KV - kbase2; if (kcols2 > 64) kcols2 = 64;
#pragma unroll
                    for (int i = 0; i < 8; i++) {
                        const int idx = tid + i * 256;
                        const int r = idx >> 4;
                        const int c4 = idx & 15;
                        const int gr = row0 + r;
                        const bool valid = (gr < M) && (c4 * 4 < kcols2);
                        const float* gsrc = valid
                            ? (A + (size_t)gr * lda + kbase2 + c4 * 4) : A;
                        cp_async16(sb + SM_STAGE + idx * 16, gsrc, valid ? 16 : 0);
                    }
                    CP_COMMIT();
                }
            }
            __syncthreads();

            // ---- compute ----
            for (int ks = 0; ks < ksteps; ks++) {
                uint32_t ah[2][4];
                {
                    const int rr = (lane & 15);
                    const int colb = ks * 32 + (lane & 16);
#pragma unroll
                    for (int mt = 0; mt < 2; mt++) {
                        const int row = wm * 32 + mt * 16 + rr;
                        const uint32_t ad = (uint32_t)(row * 128 +
                                           (colb ^ ((row & 7) << 4)));
                        ldsm4(ah[mt], sb + SM_A + ad);
                    }
                }
#pragma unroll
                for (int np = 0; np < 4; np++) {
                    const int nb = wn * 64 + np * 16;
                    const int n = nb + (lane & 7) + ((lane & 16) >> 1);
                    const int colb = ks * 32 + ((lane & 8) << 1);
                    const uint32_t bd = (uint32_t)(n * 128 + (colb ^ ((n & 7) << 4)));
                    uint32_t bh[4];
                    ldsm4(bh, sb + SM_B + bd);
#pragma unroll
                    for (int mt = 0; mt < 2; mt++) {
#pragma unroll
                        for (int nt = 0; nt < 2; nt++) {
                            mma16816h(acc[mt][np * 2 + nt], ah[mt],
                                      bh[nt * 2], bh[nt * 2 + 1]);
                        }
                    }
                }
            }
            __syncthreads();
        }

        // ---- epilogue ----
        const int quad = lane >> 2;
        const int tq = lane & 3;
#pragma unroll
        for (int mt = 0; mt < 2; mt++) {
#pragma unroll
            for (int half8 = 0; half8 < 2; half8++) {
                const int gr = row0 + wm * 32 + mt * 16 + half8 * 8 + quad;
                if (gr >= M) continue;
                if (mode == 0) {
                    float* po = out + (size_t)gr * ostride + colofsH + wn * 64;
                    float* pa = (aux && gr < rows_aux)
                              ? aux + (size_t)gr * 512 + aofs + wn * 64 : nullptr;
#pragma unroll
                    for (int j = 0; j < 8; j++) {
                        const int col = j * 8 + tq * 2;
                        float c0 = acc[mt][j][half8 * 2 + 0] + __ldg(biasH + wn * 64 + col);
                        float c1 = acc[mt][j][half8 * 2 + 1] + __ldg(biasH + wn * 64 + col + 1);
                        float2 o;
                        o.x = act ? leaky(c0) : c0;
                        o.y = act ? leaky(c1) : c1;
                        *(float2*)(po + col) = o;
                        if (pa) *(float2*)(pa + col) = o;
                    }
                } else {
                    const float id = __ldg(inv + gr);
                    const float dg = __ldg(dis + gr);
                    __half2* pi = ibuf + (size_t)gr * 64 + wn * 32;
                    __half2* py = ybuf + (size_t)gr * 64 + wn * 32;
#pragma unroll
                    for (int j = 0; j < 8; j++) {
                        const int col = j * 8 + tq * 2;
                        float xl0 = acc[mt][j][half8 * 2 + 0] + __ldg(bias + wn * 64 + col);
                        float xl1 = acc[mt][j][half8 * 2 + 1] + __ldg(bias + wn * 64 + col + 1);
                        pi[col >> 1] = __floats2half2_rn(
                            relu_(xl0 + __ldg(root + wn * 64 + col)) * id,
                            relu_(xl1 + __ldg(root + wn * 64 + col + 1)) * id);
                        py[col >> 1] = __floats2half2_rn(dg * relu_(xl0), dg * relu_(xl1));
                    }
                }
            }
        }
    }
}

// ---------------------------------------------------------------------------
// CSR gather helpers (R12 version — empirically best at avg degree ~3)
// ---------------------------------------------------------------------------
__device__ __forceinline__ float4 gather_sum(const __half2* __restrict__ y,
                                             const int* __restrict__ src,
                                             int o, int k, int lane) {
    float4 na = make_float4(0.f, 0.f, 0.f, 0.f);
    int j = 0;
    for (; j + 2 <= k; j += 2) {
        const int s0 = __ldg(src + o + j);
        const int s1 = __ldg(src + o + j + 1);
        const uint2 v0 = *(const uint2*)(y + (size_t)s0 * 64 + lane * 2);
        const uint2 v1 = *(const uint2*)(y + (size_t)s1 * 64 + lane * 2);
        float2 a0 = __half22float2(*(const __half2*)&v0.x);
        float2 a1 = __half22float2(*(const __half2*)&v0.y);
        float2 b0 = __half22float2(*(const __half2*)&v1.x);
        float2 b1 = __half22float2(*(const __half2*)&v1.y);
        na.x += a0.x + b0.x;
        na.y += a0.y + b0.y;
        na.z += a1.x + b1.x;
        na.w += a1.y + b1.y;
    }
    if (j < k) {
        const int s0 = __ldg(src + o + j);
        const uint2 v0 = *(const uint2*)(y + (size_t)s0 * 64 + lane * 2);
        float2 a0 = __half22float2(*(const __half2*)&v0.x);
        float2 a1 = __half22float2(*(const __half2*)&v0.y);
        na.x += a0.x; na.y += a0.y; na.z += a1.x; na.w += a1.y;
    }
    return na;
}

__device__ __forceinline__ float4 load_init_h(const __half2* __restrict__ ibuf,
                                              int c, int lane) {
    const uint2 iv = *(const uint2*)(ibuf + (size_t)c * 64 + lane * 2);
    float2 i0 = __half22float2(*(const __half2*)&iv.x);
    float2 i1 = __half22float2(*(const __half2*)&iv.y);
    return make_float4(i0.x, i0.y, i1.x, i1.y);
}

// ---------------------------------------------------------------------------
// Pass-A aggregation: agg[c] = init[c] + dis[c] * sum YA[src]   (fp32 out)
// ---------------------------------------------------------------------------
__global__ void agg_kernel(const __half2* __restrict__ ibuf,
                           const __half2* __restrict__ y,
                           const int* __restrict__ offs,
                           const int* __restrict__ cnt,
                           const int* __restrict__ src,
                           const float* __restrict__ dis,
                           float* __restrict__ agg, int Nn, int obase) {
    const int c = blockIdx.x * 8 + (threadIdx.x >> 5);
    if (c >= Nn) return;
    const int lane = threadIdx.x & 31;

    float4 acc = load_init_h(ibuf, c, lane);
    const int o = __ldg(offs + obase + c);
    const int k = __ldg(cnt + obase + c);
    const float dc = __ldg(dis + c);
    float4 na = gather_sum(y, src, o, k, lane);
    acc.x += dc * na.x; acc.y += dc * na.y;
    acc.z += dc * na.z; acc.w += dc * na.w;
    ((float4*)agg)[(size_t)c * 32 + lane] = acc;
}

// ---------------------------------------------------------------------------
// Pass-B aggregation + LayerNorm + LeakyReLU + residual.
// ---------------------------------------------------------------------------
__global__ void agg_ln_kernel(const __half2* __restrict__ ibuf,
                              const __half2* __restrict__ y,
                              const int* __restrict__ offs,
                              const int* __restrict__ cnt,
                              const int* __restrict__ src,
                              const float* __restrict__ dis,
                              const float* __restrict__ g,
                              const float* __restrict__ b,
                              const float* __restrict__ hprev,
                              float* __restrict__ hnext, int hstride, int hofs,
                              float* __restrict__ aux, int aofs, int rows_aux,
                              int Nn, int obase) {
    const int c = blockIdx.x * 8 + (threadIdx.x >> 5);
    if (c >= Nn) return;
    const int lane = threadIdx.x & 31;

    float4 acc = load_init_h(ibuf, c, lane);
    const int o = __ldg(offs + obase + c);
    const int k = __ldg(cnt + obase + c);
    const float dc = __ldg(dis + c);
    float4 na = gather_sum(y, src, o, k, lane);
    acc.x += dc * na.x; acc.y += dc * na.y;
    acc.z += dc * na.z; acc.w += dc * na.w;

    float s1 = acc.x + acc.y + acc.z + acc.w;
#pragma unroll
    for (int off = 16; off > 0; off >>= 1) s1 += __shfl_xor_sync(0xffffffffu, s1, off);
    const float mu = s1 * (1.0f / 128.0f);
    float dx = acc.x - mu, dy = acc.y - mu, dz = acc.z - mu, dw = acc.w - mu;
    float q = dx * dx + dy * dy + dz * dz + dw * dw;
#pragma unroll
    for (int off = 16; off > 0; off >>= 1) q += __shfl_xor_sync(0xffffffffu, q, off);
    const float rstd = rsqrtf(q * (1.0f / 128.0f) + LN_EPS);

    float4 gg = ((const float4*)g)[lane];
    float4 bb = ((const float4*)b)[lane];
    float4 hp = ((const float4*)hprev)[(size_t)c * 32 + lane];
    float4 out;
    out.x = leaky(dx * rstd * gg.x + bb.x) + hp.x;
    out.y = leaky(dy * rstd * gg.y + bb.y) + hp.y;
    out.z = leaky(dz * rstd * gg.z + bb.z) + hp.z;
    out.w = leaky(dw * rstd * gg.w + bb.w) + hp.w;
    ((float4*)(hnext + (size_t)c * hstride + hofs))[lane] = out;
    if (aux && c < rows_aux)
        ((float4*)(aux + (size_t)c * 512 + aofs))[lane] = out;
}

// ---------------------------------------------------------------------------
// Launch
// ---------------------------------------------------------------------------
extern "C" void kernel_launch(void* const* d_in, const int* in_sizes, int n_in,
                              void* d_out, int out_size) {
    const float* x        = (const float*)d_in[0];
    const float* enc_w1   = (const float*)d_in[1];
    const float* enc_b1   = (const float*)d_in[2];
    const float* enc_w2   = (const float*)d_in[3];
    const float* enc_b2   = (const float*)d_in[4];
    const float* conv_w   = (const float*)d_in[5];
    const float* conv_b   = (const float*)d_in[6];
    const float* conv_rt  = (const float*)d_in[7];
    const float* reconv_w = (const float*)d_in[8];
    const float* reconv_b = (const float*)d_in[9];
    const float* reconv_rt= (const float*)d_in[10];
    const float* ln_g     = (const float*)d_in[11];
    const float* ln_b     = (const float*)d_in[12];
    const int*   eA       = (const int*)d_in[13];
    const int*   eB       = (const int*)d_in[14];

    const int N  = in_sizes[0] / 32;
    const int Ea = in_sizes[13] / 2;
    const int Eb = in_sizes[14] / 2;
    const int rows_out = out_size / 512;

    const int* rowsA = eA; const int* colsA = eA + Ea;
    const int* rowsB = eB; const int* colsB = eB + Eb;

    void* p;
    cudaGetSymbolAddress(&p, g_H);    float* H    = (float*)p;
    cudaGetSymbolAddress(&p, g_AGG);  float* AGG  = (float*)p;
    cudaGetSymbolAddress(&p, g_H1);   float* H1E  = (float*)p;
    cudaGetSymbolAddress(&p, g_YA);   __half2* YA = (__half2*)p;
    cudaGetSymbolAddress(&p, g_YB);   __half2* YB = (__half2*)p;
    cudaGetSymbolAddress(&p, g_IN);   __half2* IN = (__half2*)p;
    cudaGetSymbolAddress(&p, g_disA); float* disA = (float*)p;
    cudaGetSymbolAddress(&p, g_disB); float* disB = (float*)p;
    cudaGetSymbolAddress(&p, g_invA); float* invA = (float*)p;
    cudaGetSymbolAddress(&p, g_invB); float* invB = (float*)p;
    cudaGetSymbolAddress(&p, g_icsr); int* icsr   = (int*)p;
    cudaGetSymbolAddress(&p, g_offs); int* offs   = (int*)p;
    cudaGetSymbolAddress(&p, g_src);  int* src    = (int*)p;
    cudaGetSymbolAddress(&p, g_bsums);int* bsums  = (int*)p;
    cudaGetSymbolAddress(&p, g_W16);  __half* W16 = (__half*)p;

    int* rowcntA = icsr;
    int* rowcntB = icsr + NMAX;
    int* colcnt  = icsr + 2 * NMAX;
    int* cursor  = icsr + 4 * NMAX;

    const size_t hstride = (size_t)NMAX * EMB;
    float* dout = (float*)d_out;

    cudaFuncSetAttribute(gemm_tc_kernel,
                         cudaFuncAttributeMaxDynamicSharedMemorySize, SMEM_TC);

    // ---- side stream for the CSR build (overlaps with encoder GEMMs) ----
    static cudaStream_t s2 = nullptr;
    static cudaEvent_t ev_fork = nullptr, ev_join = nullptr;
    if (!s2) {
        cudaStreamCreateWithFlags(&s2, cudaStreamNonBlocking);
        cudaEventCreateWithFlags(&ev_fork, cudaEventDisableTiming);
        cudaEventCreateWithFlags(&ev_join, cudaEventDisableTiming);
    }

    cudaEventRecord(ev_fork, 0);
    cudaStreamWaitEvent(s2, ev_fork, 0);

    // ---- CSR build + degrees (side stream) ----
    zero_kernel<<<(6 * NMAX + 255) / 256, 256, 0, s2>>>(icsr, 6 * NMAX);
    hist2_kernel<<<(Ea + 255) / 256, 256, 0, s2>>>(rowsA, colsA, rowcntA, colcnt, Ea);
    hist2_kernel<<<(Eb + 255) / 256, 256, 0, s2>>>(rowsB, colsB, rowcntB,
                                                   colcnt + NMAX, Eb);
    deg_fin_kernel<<<(N + 255) / 256, 256, 0, s2>>>(rowcntA, disA, invA, N);
    deg_fin_kernel<<<(N + 255) / 256, 256, 0, s2>>>(rowcntB, disB, invB, N);
    {
        const int n2 = 2 * NMAX;
        const int nb = (n2 + 1023) / 1024;
        scan_block_kernel<<<nb, 256, 0, s2>>>(colcnt, offs, bsums, n2);
        scan_sums_kernel<<<1, 512, 0, s2>>>(bsums, nb);
        scan_add_kernel<<<(n2 + 255) / 256, 256, 0, s2>>>(offs, bsums, n2);
    }
    fill_kernel<<<(Ea + 255) / 256, 256, 0, s2>>>(rowsA, colsA, offs, cursor, src,
                                                  Ea, 0);
    fill_kernel<<<(Eb + 255) / 256, 256, 0, s2>>>(rowsB, colsB, offs, cursor, src,
                                                  Eb, NMAX);
    cudaEventRecord(ev_join, s2);

    // ---- weight prep + encoder (main stream, concurrent with CSR build) ----
    prep_all_kernel<<<18 * 32, 256>>>(enc_w1, enc_w2, conv_w, reconv_w, W16);

    const int tiles = (N + 127) / 128;

    // enc1: single launch covering both N-halves (A tile staged once)
    gemm_tc_kernel<<<tiles, 256, SMEM_TC>>>(x, 32, N,
        W16 + 0 * 8192, 1, 32, enc_b1, H1E, 256, 0, 1,
        nullptr, 0, 0, 0, nullptr, nullptr, nullptr, nullptr, nullptr,
        W16 + 1 * 8192, enc_b1 + 128, 128);
    // enc2 -> H0 + JK slice 0 of d_out
    gemm_tc_kernel<<<tiles, 256, SMEM_TC>>>(H1E, 256, N,
        W16 + 2 * 8192, 4, 256, enc_b2, H, 128, 0, 1,
        dout, 0, rows_out, 0, nullptr, nullptr, nullptr, nullptr, nullptr,
        nullptr, nullptr, 0);

    // join: GCN layers need the CSR
    cudaStreamWaitEvent(0, ev_join, 0);

    // ---- GCN layers ----
    for (int l = 0; l < 3; l++) {
        const float* hl = H + (size_t)l * hstride;
        float* hn = H + (size_t)(l + 1) * hstride;
        const int last = (l == 2);

        // conv (edge set A): GEMM -> IN (half init) + YA
        gemm_tc_kernel<<<tiles, 256, SMEM_TC>>>(hl, 128, N,
            W16 + (6 + 2 * l) * 8192, 2, 128,
            conv_b + l * EMB, nullptr, 0, 0, 0,
            nullptr, 0, 0, 1, conv_rt + l * EMB, disA, invA, YA, IN,
            nullptr, nullptr, 0);
        agg_kernel<<<(N + 7) / 8, 256>>>(IN, YA, offs, colcnt, src, disA, AGG, N, 0);

        // reconv (edge set B): GEMM reads AGG -> IN (half init, reused) + YB
        gemm_tc_kernel<<<tiles, 256, SMEM_TC>>>(AGG, 128, N,
            W16 + (12 + 2 * l) * 8192, 2, 128,
            reconv_b + l * EMB, nullptr, 0, 0, 0,
            nullptr, 0, 0, 1, reconv_rt + l * EMB, disB, invB, YB, IN,
            nullptr, nullptr, 0);

        if (!last) {
            agg_ln_kernel<<<(N + 7) / 8, 256>>>(IN, YB, offs, colcnt, src, disB,
                ln_g + l * EMB, ln_b + l * EMB, hl,
                hn, 128, 0, dout, (l + 1) * 128, rows_out, N, NMAX);
        } else {
            agg_ln_kernel<<<(rows_out + 7) / 8, 256>>>(IN, YB, offs, colcnt, src, disB,
                ln_g + l * EMB, ln_b + l * EMB, hl,
                dout, 512, 384, nullptr, 0, 0, rows_out, NMAX);
        }
    }
}

// round 17
// speedup vs baseline: 1.4135x; 1.0429x over previous
#include <cuda_runtime.h>
#include <cuda_bf16.h>
#include <cuda_fp16.h>
#include <cstddef>
#include <cstdint>

// ---------------------------------------------------------------------------
// Problem constants
// ---------------------------------------------------------------------------
#define NMAX   200000
#define EMAX   650000
#define EMB    128
#define ENC1   256
#define NEG_SLOPE 0.1f
#define LN_EPS 1e-5f

// ---------------------------------------------------------------------------
// Scratch (static __device__ arrays; no allocations allowed)
// ---------------------------------------------------------------------------
__device__ float g_H[4][(size_t)NMAX * EMB];   // h_list[0..3]
__device__ __half2 g_AGGH[(size_t)NMAX * 64];  // pass-A aggregated output (fp16)
__device__ float g_H1[(size_t)NMAX * ENC1];    // encoder intermediate
__device__ __half2 g_YA[(size_t)NMAX * 64];    // fp16 messages, pass A
__device__ __half2 g_YB[(size_t)NMAX * 64];    // fp16 messages, pass B
__device__ __half2 g_IN[(size_t)NMAX * 64];    // fp16 init (self term), reused A/B
__device__ float g_disA[NMAX];
__device__ float g_disB[NMAX];
__device__ float g_invA[NMAX];
__device__ float g_invB[NMAX];
// CSR scratch: [0,N) rowcntA | [N,2N) rowcntB | [2N,4N) colcnt (A then B)
//              [4N,6N) cursors (A then B)
__device__ int g_icsr[6 * NMAX];
__device__ int g_offs[2 * NMAX];
__device__ int g_src[2 * EMAX];
__device__ int g_bsums[512];
// Prepped weight chunks: 18 chunks of [128 n x 64 k] fp16, XOR-swizzled.
__device__ __half g_W16[18 * 8192];

// ---------------------------------------------------------------------------
// Helpers
// ---------------------------------------------------------------------------
__device__ __forceinline__ float leaky(float v) {
    return v >= 0.0f ? v : NEG_SLOPE * v;
}
__device__ __forceinline__ float relu_(float v) { return fmaxf(v, 0.0f); }

__device__ __forceinline__ uint32_t smem_u32(const void* p) {
    uint32_t a;
    asm("{ .reg .u64 t; cvta.to.shared.u64 t, %1; cvt.u32.u64 %0, t; }"
        : "=r"(a) : "l"(p));
    return a;
}

__device__ __forceinline__ void ldsm4(uint32_t* r, uint32_t addr) {
    asm volatile("ldmatrix.sync.aligned.m8n8.x4.shared.b16 {%0,%1,%2,%3}, [%4];"
                 : "=r"(r[0]), "=r"(r[1]), "=r"(r[2]), "=r"(r[3]) : "r"(addr));
}

// fp16 tensor-core MMA, fp32 accumulate
__device__ __forceinline__ void mma16816h(float* c, const uint32_t* a,
                                          uint32_t b0, uint32_t b1) {
    asm volatile(
        "mma.sync.aligned.m16n8k16.row.col.f32.f16.f16.f32 "
        "{%0,%1,%2,%3}, {%4,%5,%6,%7}, {%8,%9}, {%0,%1,%2,%3};"
        : "+f"(c[0]), "+f"(c[1]), "+f"(c[2]), "+f"(c[3])
        : "r"(a[0]), "r"(a[1]), "r"(a[2]), "r"(a[3]), "r"(b0), "r"(b1));
}

__device__ __forceinline__ void cp_async16(uint32_t smaddr, const void* g,
                                           int srcsize) {
    asm volatile("cp.async.cg.shared.global [%0], [%1], 16, %2;"
                 :: "r"(smaddr), "l"(g), "r"(srcsize));
}
#define CP_COMMIT() asm volatile("cp.async.commit_group;" ::: "memory")
#define CP_WAIT0()  asm volatile("cp.async.wait_group 0;" ::: "memory")

// fp32x4 -> swizzled fp16x4 store
__device__ __forceinline__ void store_h16(char* smbase, int off, float4 v) {
    __half2 h01 = __floats2half2_rn(v.x, v.y);
    __half2 h23 = __floats2half2_rn(v.z, v.w);
    *(uint2*)(smbase + off) = make_uint2(*reinterpret_cast<uint32_t*>(&h01),
                                         *reinterpret_cast<uint32_t*>(&h23));
}

// ---------------------------------------------------------------------------
// CSR build kernels
// ---------------------------------------------------------------------------
__global__ void zero_kernel(int* p, int n) {
    int i = blockIdx.x * blockDim.x + threadIdx.x;
    if (i < n) p[i] = 0;
}

__global__ void hist2_kernel(const int* __restrict__ rows,
                             const int* __restrict__ cols,
                             int* __restrict__ rowcnt,
                             int* __restrict__ colcnt, int E) {
    int e = blockIdx.x * blockDim.x + threadIdx.x;
    if (e >= E) return;
    atomicAdd(&rowcnt[rows[e]], 1);
    atomicAdd(&colcnt[cols[e]], 1);
}

__global__ void deg_fin_kernel(const int* __restrict__ cnt,
                               float* __restrict__ dis,
                               float* __restrict__ inv, int n) {
    int i = blockIdx.x * blockDim.x + threadIdx.x;
    if (i < n) {
        float d = (float)(cnt[i] + 1);
        dis[i] = rsqrtf(d);
        inv[i] = 1.0f / d;
    }
}

__global__ void scan_block_kernel(const int* __restrict__ in, int* __restrict__ out,
                                  int* __restrict__ bsums, int n) {
    __shared__ int sh[256];
    const int base = blockIdx.x * 1024;
    const int t = threadIdx.x;
    int v[4]; int s = 0;
#pragma unroll
    for (int j = 0; j < 4; j++) {
        int i = base + t * 4 + j;
        v[j] = (i < n) ? in[i] : 0;
        s += v[j];
    }
    sh[t] = s;
    __syncthreads();
    for (int off = 1; off < 256; off <<= 1) {
        int x = (t >= off) ? sh[t - off] : 0;
        __syncthreads();
        sh[t] += x;
        __syncthreads();
    }
    int run = (t > 0) ? sh[t - 1] : 0;
    if (t == 255) bsums[blockIdx.x] = sh[255];
#pragma unroll
    for (int j = 0; j < 4; j++) {
        int i = base + t * 4 + j;
        if (i < n) out[i] = run;
        run += v[j];
    }
}

__global__ void scan_sums_kernel(int* bsums, int nb) {
    __shared__ int sh[512];
    int t = threadIdx.x;
    sh[t] = (t < nb) ? bsums[t] : 0;
    __syncthreads();
    for (int off = 1; off < 512; off <<= 1) {
        int x = (t >= off) ? sh[t - off] : 0;
        __syncthreads();
        sh[t] += x;
        __syncthreads();
    }
    if (t < nb) bsums[t] = (t > 0) ? sh[t - 1] : 0;
}

__global__ void scan_add_kernel(int* __restrict__ out, const int* __restrict__ bsums,
                                int n) {
    int i = blockIdx.x * blockDim.x + threadIdx.x;
    if (i < n) out[i] += bsums[i >> 10];
}

__global__ void fill_kernel(const int* __restrict__ rows, const int* __restrict__ cols,
                            const int* __restrict__ offs, int* __restrict__ cursor,
                            int* __restrict__ src, int E, int obase) {
    int e = blockIdx.x * blockDim.x + threadIdx.x;
    if (e >= E) return;
    int c = cols[e];
    int pos = offs[obase + c] + atomicAdd(&cursor[obase + c], 1);
    src[pos] = rows[e];
}

// ---------------------------------------------------------------------------
// Merged weight prep: 18 chunks of [128n x 64k], swizzled fp16
// ---------------------------------------------------------------------------
__global__ void prep_all_kernel(const float* __restrict__ enc_w1,
                                const float* __restrict__ enc_w2,
                                const float* __restrict__ conv_w,
                                const float* __restrict__ reconv_w,
                                __half* __restrict__ W16) {
    const int chunk = blockIdx.x >> 5;
    const int idx = (blockIdx.x & 31) * 256 + threadIdx.x;
    const int n = idx >> 6;
    const int k = idx & 63;
    const float* W; int ldn, k0, n0, kcount;
    if (chunk < 2)      { W = enc_w1; ldn = 256; k0 = 0; n0 = chunk * 128; kcount = 32; }
    else if (chunk < 6) { W = enc_w2; ldn = 128; k0 = (chunk - 2) * 64; n0 = 0; kcount = 64; }
    else if (chunk < 12) {
        int l = (chunk - 6) >> 1, c = (chunk - 6) & 1;
        W = conv_w + (size_t)l * 16384; ldn = 128; k0 = c * 64; n0 = 0; kcount = 64;
    } else {
        int l = (chunk - 12) >> 1, c = (chunk - 12) & 1;
        W = reconv_w + (size_t)l * 16384; ldn = 128; k0 = c * 64; n0 = 0; kcount = 64;
    }
    float v = (k < kcount) ? W[(size_t)(k0 + k) * ldn + n0 + n] : 0.0f;
    int off = n * 128 + ((k * 2) ^ ((n & 7) << 4));
    W16[(size_t)chunk * 8192 + (off >> 1)] = __float2half_rn(v);
}

// ---------------------------------------------------------------------------
// Tensor-core GEMM (mma.sync fp16, fp32 accum) with cp.async A pipeline.
//  ahalf=0: A fp32, staged via SM_STAGE with fp32->fp16 convert.
//  ahalf=1: A fp16 (row stride 128 halfs), cp.async lands DIRECTLY in the
//           swizzled operand buffers (chunk ck at SM_STAGE + ck*16KB);
//           all chunks prefetched at entry. kchunks <= 2.
//  mode 0: out[gr*ostride+colofs+n] = act? leaky(d) : d
//          if (aux && gr<rows_aux) also aux[gr*512+aofs+n]
//  mode 1 (GCN prep): ibuf[gr][n] = half( relu(d+root[n]) * inv[gr] )  (init)
//                     ybuf[gr][n] = half( dis[gr] * relu(d) )          (message)
//  Optional second half (W2 != null, requires kchunks==1, mode 0, ahalf 0).
// ---------------------------------------------------------------------------
#define SM_A     0
#define SM_B     16384
#define SM_STAGE 32768
#define SMEM_TC  65536

__global__ void __launch_bounds__(256, 2)
gemm_tc_kernel(const float* __restrict__ A, int lda, int M, int ahalf,
               const __half* __restrict__ WG,
               int kchunks, int KV,
               const float* __restrict__ bias,
               float* __restrict__ out, int ostride, int colofs, int act,
               float* __restrict__ aux, int aofs, int rows_aux,
               int mode,
               const float* __restrict__ root,
               const float* __restrict__ dis,
               const float* __restrict__ inv,
               __half2* __restrict__ ybuf,
               __half2* __restrict__ ibuf,
               const __half* __restrict__ W2,
               const float* __restrict__ bias2, int colofs2) {
    extern __shared__ char sm[];
    const uint32_t sb = smem_u32(sm);
    const int tid = threadIdx.x;
    const int w = tid >> 5;
    const int lane = tid & 31;
    const int wm = w & 3;
    const int wn = w >> 2;
    const int row0 = blockIdx.x * 128;
    const int nhalves = W2 ? 2 : 1;

    // ---- prefetch A via cp.async ----
    if (!ahalf) {
        const int kcols0 = (KV < 64) ? KV : 64;
#pragma unroll
        for (int i = 0; i < 8; i++) {
            const int idx = tid + i * 256;
            const int r = idx >> 4;
            const int c4 = idx & 15;
            const int gr = row0 + r;
            const bool valid = (gr < M) && (c4 * 4 < kcols0);
            const float* gsrc = valid ? (A + (size_t)gr * lda + c4 * 4) : A;
            cp_async16(sb + SM_STAGE + idx * 16, gsrc, valid ? 16 : 0);
        }
        CP_COMMIT();
    } else {
        // fp16 A: land each chunk directly in its swizzled buffer.
        const __half* Ah = (const __half*)A;
        for (int ck = 0; ck < kchunks; ck++) {
#pragma unroll
            for (int i = 0; i < 4; i++) {
                const int idx = tid + i * 256;      // 0..1023
                const int r = idx >> 3;             // row 0..127
                const int c8 = idx & 7;             // col group of 8 halfs
                const int gr = row0 + r;
                const bool valid = (gr < M);
                const __half* gsrc = valid
                    ? (Ah + (size_t)gr * 128 + ck * 64 + c8 * 8) : Ah;
                const int off = r * 128 + ((c8 * 16) ^ ((r & 7) << 4));
                cp_async16(sb + SM_STAGE + ck * 16384 + off, gsrc, valid ? 16 : 0);
            }
        }
        CP_COMMIT();
    }

    for (int half = 0; half < nhalves; half++) {
        const __half* WH = half ? W2 : WG;
        const float* biasH = half ? bias2 : bias;
        const int colofsH = half ? colofs2 : colofs;

        float acc[2][8][4];
#pragma unroll
        for (int a = 0; a < 2; a++)
#pragma unroll
            for (int b = 0; b < 8; b++)
#pragma unroll
                for (int c = 0; c < 4; c++) acc[a][b][c] = 0.0f;

        for (int ck = 0; ck < kchunks; ck++) {
            int kcols = KV - ck * 64; if (kcols > 64) kcols = 64;
            const int ksteps = (kcols + 15) >> 4;

            if (half > 0) __syncthreads();   // protect B buffer reuse

            // ---- stage B chunk (16 KB raw copy) ----
            {
                const float4* shg = (const float4*)(WH + (size_t)ck * 8192);
                float4* dh = (float4*)(sm + SM_B);
                for (int i = tid; i < 1024; i += 256) dh[i] = shg[i];
            }

            uint32_t abase;
            if (!ahalf) {
                abase = sb + SM_A;
                // wait cp.async, convert from SMEM stage
                CP_WAIT0();
#pragma unroll
                for (int i = 0; i < 8; i++) {
                    const int idx = tid + i * 256;
                    const int r = idx >> 4;
                    const int c4 = idx & 15;
                    float4 v = *(const float4*)(sm + SM_STAGE + idx * 16);
                    int off = r * 128 + ((c4 * 8) ^ ((r & 7) << 4));
                    store_h16(sm + SM_A, off, v);
                }
                // prefetch next chunk (overlaps compute below)
                if (ck + 1 < kchunks) {
                    const int kbase2 = (ck + 1) * 64;
                    int kcols2 = KV - kbase2; if (kcols2 > 64) kcols2 = 64;
#pragma unroll
                    for (int i = 0; i < 8; i++) {
                        const int idx = tid + i * 256;
                        const int r = idx >> 4;
                        const int c4 = idx & 15;
                        const int gr = row0 + r;
                        const bool valid = (gr < M) && (c4 * 4 < kcols2);
                        const float* gsrc = valid
                            ? (A + (size_t)gr * lda + kbase2 + c4 * 4) : A;
                        cp_async16(sb + SM_STAGE + idx * 16, gsrc, valid ? 16 : 0);
                    }
                    CP_COMMIT();
                }
            } else {
                abase = sb + SM_STAGE + ck * 16384;
                if (ck == 0) CP_WAIT0();   // all A chunks in flight complete
            }
            __syncthreads();

            // ---- compute ----
            for (int ks = 0; ks < ksteps; ks++) {
                uint32_t ah[2][4];
                {
                    const int rr = (lane & 15);
                    const int colb = ks * 32 + (lane & 16);
#pragma unroll
                    for (int mt = 0; mt < 2; mt++) {
                        const int row = wm * 32 + mt * 16 + rr;
                        const uint32_t ad = (uint32_t)(row * 128 +
                                           (colb ^ ((row & 7) << 4)));
                        ldsm4(ah[mt], abase + ad);
                    }
                }
#pragma unroll
                for (int np = 0; np < 4; np++) {
                    const int nb = wn * 64 + np * 16;
                    const int n = nb + (lane & 7) + ((lane & 16) >> 1);
                    const int colb = ks * 32 + ((lane & 8) << 1);
                    const uint32_t bd = (uint32_t)(n * 128 + (colb ^ ((n & 7) << 4)));
                    uint32_t bh[4];
                    ldsm4(bh, sb + SM_B + bd);
#pragma unroll
                    for (int mt = 0; mt < 2; mt++) {
#pragma unroll
                        for (int nt = 0; nt < 2; nt++) {
                            mma16816h(acc[mt][np * 2 + nt], ah[mt],
                                      bh[nt * 2], bh[nt * 2 + 1]);
                        }
                    }
                }
            }
            __syncthreads();
        }

        // ---- epilogue ----
        const int quad = lane >> 2;
        const int tq = lane & 3;
#pragma unroll
        for (int mt = 0; mt < 2; mt++) {
#pragma unroll
            for (int half8 = 0; half8 < 2; half8++) {
                const int gr = row0 + wm * 32 + mt * 16 + half8 * 8 + quad;
                if (gr >= M) continue;
                if (mode == 0) {
                    float* po = out + (size_t)gr * ostride + colofsH + wn * 64;
                    float* pa = (aux && gr < rows_aux)
                              ? aux + (size_t)gr * 512 + aofs + wn * 64 : nullptr;
#pragma unroll
                    for (int j = 0; j < 8; j++) {
                        const int col = j * 8 + tq * 2;
                        float c0 = acc[mt][j][half8 * 2 + 0] + __ldg(biasH + wn * 64 + col);
                        float c1 = acc[mt][j][half8 * 2 + 1] + __ldg(biasH + wn * 64 + col + 1);
                        float2 o;
                        o.x = act ? leaky(c0) : c0;
                        o.y = act ? leaky(c1) : c1;
                        *(float2*)(po + col) = o;
                        if (pa) *(float2*)(pa + col) = o;
                    }
                } else {
                    const float id = __ldg(inv + gr);
                    const float dg = __ldg(dis + gr);
                    __half2* pi = ibuf + (size_t)gr * 64 + wn * 32;
                    __half2* py = ybuf + (size_t)gr * 64 + wn * 32;
#pragma unroll
                    for (int j = 0; j < 8; j++) {
                        const int col = j * 8 + tq * 2;
                        float xl0 = acc[mt][j][half8 * 2 + 0] + __ldg(bias + wn * 64 + col);
                        float xl1 = acc[mt][j][half8 * 2 + 1] + __ldg(bias + wn * 64 + col + 1);
                        pi[col >> 1] = __floats2half2_rn(
                            relu_(xl0 + __ldg(root + wn * 64 + col)) * id,
                            relu_(xl1 + __ldg(root + wn * 64 + col + 1)) * id);
                        py[col >> 1] = __floats2half2_rn(dg * relu_(xl0), dg * relu_(xl1));
                    }
                }
            }
        }
    }
}

// ---------------------------------------------------------------------------
// CSR gather helpers (R12 version — empirically best at avg degree ~3)
// ---------------------------------------------------------------------------
__device__ __forceinline__ float4 gather_sum(const __half2* __restrict__ y,
                                             const int* __restrict__ src,
                                             int o, int k, int lane) {
    float4 na = make_float4(0.f, 0.f, 0.f, 0.f);
    int j = 0;
    for (; j + 2 <= k; j += 2) {
        const int s0 = __ldg(src + o + j);
        const int s1 = __ldg(src + o + j + 1);
        const uint2 v0 = *(const uint2*)(y + (size_t)s0 * 64 + lane * 2);
        const uint2 v1 = *(const uint2*)(y + (size_t)s1 * 64 + lane * 2);
        float2 a0 = __half22float2(*(const __half2*)&v0.x);
        float2 a1 = __half22float2(*(const __half2*)&v0.y);
        float2 b0 = __half22float2(*(const __half2*)&v1.x);
        float2 b1 = __half22float2(*(const __half2*)&v1.y);
        na.x += a0.x + b0.x;
        na.y += a0.y + b0.y;
        na.z += a1.x + b1.x;
        na.w += a1.y + b1.y;
    }
    if (j < k) {
        const int s0 = __ldg(src + o + j);
        const uint2 v0 = *(const uint2*)(y + (size_t)s0 * 64 + lane * 2);
        float2 a0 = __half22float2(*(const __half2*)&v0.x);
        float2 a1 = __half22float2(*(const __half2*)&v0.y);
        na.x += a0.x; na.y += a0.y; na.z += a1.x; na.w += a1.y;
    }
    return na;
}

__device__ __forceinline__ float4 load_init_h(const __half2* __restrict__ ibuf,
                                              int c, int lane) {
    const uint2 iv = *(const uint2*)(ibuf + (size_t)c * 64 + lane * 2);
    float2 i0 = __half22float2(*(const __half2*)&iv.x);
    float2 i1 = __half22float2(*(const __half2*)&iv.y);
    return make_float4(i0.x, i0.y, i1.x, i1.y);
}

// ---------------------------------------------------------------------------
// Pass-A aggregation: aggh[c] = half( init[c] + dis[c] * sum YA[src] )
// (round-once: identical to fp32 store + fp16 convert at GEMM staging)
// ---------------------------------------------------------------------------
__global__ void agg_kernel(const __half2* __restrict__ ibuf,
                           const __half2* __restrict__ y,
                           const int* __restrict__ offs,
                           const int* __restrict__ cnt,
                           const int* __restrict__ src,
                           const float* __restrict__ dis,
                           __half2* __restrict__ aggh, int Nn, int obase) {
    const int c = blockIdx.x * 8 + (threadIdx.x >> 5);
    if (c >= Nn) return;
    const int lane = threadIdx.x & 31;

    float4 acc = load_init_h(ibuf, c, lane);
    const int o = __ldg(offs + obase + c);
    const int k = __ldg(cnt + obase + c);
    const float dc = __ldg(dis + c);
    float4 na = gather_sum(y, src, o, k, lane);
    acc.x += dc * na.x; acc.y += dc * na.y;
    acc.z += dc * na.z; acc.w += dc * na.w;
    __half2 h01 = __floats2half2_rn(acc.x, acc.y);
    __half2 h23 = __floats2half2_rn(acc.z, acc.w);
    *(uint2*)(aggh + (size_t)c * 64 + lane * 2) =
        make_uint2(*reinterpret_cast<uint32_t*>(&h01),
                   *reinterpret_cast<uint32_t*>(&h23));
}

// ---------------------------------------------------------------------------
// Pass-B aggregation + LayerNorm + LeakyReLU + residual.
// ---------------------------------------------------------------------------
__global__ void agg_ln_kernel(const __half2* __restrict__ ibuf,
                              const __half2* __restrict__ y,
                              const int* __restrict__ offs,
                              const int* __restrict__ cnt,
                              const int* __restrict__ src,
                              const float* __restrict__ dis,
                              const float* __restrict__ g,
                              const float* __restrict__ b,
                              const float* __restrict__ hprev,
                              float* __restrict__ hnext, int hstride, int hofs,
                              float* __restrict__ aux, int aofs, int rows_aux,
                              int Nn, int obase) {
    const int c = blockIdx.x * 8 + (threadIdx.x >> 5);
    if (c >= Nn) return;
    const int lane = threadIdx.x & 31;

    float4 acc = load_init_h(ibuf, c, lane);
    const int o = __ldg(offs + obase + c);
    const int k = __ldg(cnt + obase + c);
    const float dc = __ldg(dis + c);
    float4 na = gather_sum(y, src, o, k, lane);
    acc.x += dc * na.x; acc.y += dc * na.y;
    acc.z += dc * na.z; acc.w += dc * na.w;

    float s1 = acc.x + acc.y + acc.z + acc.w;
#pragma unroll
    for (int off = 16; off > 0; off >>= 1) s1 += __shfl_xor_sync(0xffffffffu, s1, off);
    const float mu = s1 * (1.0f / 128.0f);
    float dx = acc.x - mu, dy = acc.y - mu, dz = acc.z - mu, dw = acc.w - mu;
    float q = dx * dx + dy * dy + dz * dz + dw * dw;
#pragma unroll
    for (int off = 16; off > 0; off >>= 1) q += __shfl_xor_sync(0xffffffffu, q, off);
    const float rstd = rsqrtf(q * (1.0f / 128.0f) + LN_EPS);

    float4 gg = ((const float4*)g)[lane];
    float4 bb = ((const float4*)b)[lane];
    float4 hp = ((const float4*)hprev)[(size_t)c * 32 + lane];
    float4 out;
    out.x = leaky(dx * rstd * gg.x + bb.x) + hp.x;
    out.y = leaky(dy * rstd * gg.y + bb.y) + hp.y;
    out.z = leaky(dz * rstd * gg.z + bb.z) + hp.z;
    out.w = leaky(dw * rstd * gg.w + bb.w) + hp.w;
    ((float4*)(hnext + (size_t)c * hstride + hofs))[lane] = out;
    if (aux && c < rows_aux)
        ((float4*)(aux + (size_t)c * 512 + aofs))[lane] = out;
}

// ---------------------------------------------------------------------------
// Launch
// ---------------------------------------------------------------------------
extern "C" void kernel_launch(void* const* d_in, const int* in_sizes, int n_in,
                              void* d_out, int out_size) {
    const float* x        = (const float*)d_in[0];
    const float* enc_w1   = (const float*)d_in[1];
    const float* enc_b1   = (const float*)d_in[2];
    const float* enc_w2   = (const float*)d_in[3];
    const float* enc_b2   = (const float*)d_in[4];
    const float* conv_w   = (const float*)d_in[5];
    const float* conv_b   = (const float*)d_in[6];
    const float* conv_rt  = (const float*)d_in[7];
    const float* reconv_w = (const float*)d_in[8];
    const float* reconv_b = (const float*)d_in[9];
    const float* reconv_rt= (const float*)d_in[10];
    const float* ln_g     = (const float*)d_in[11];
    const float* ln_b     = (const float*)d_in[12];
    const int*   eA       = (const int*)d_in[13];
    const int*   eB       = (const int*)d_in[14];

    const int N  = in_sizes[0] / 32;
    const int Ea = in_sizes[13] / 2;
    const int Eb = in_sizes[14] / 2;
    const int rows_out = out_size / 512;

    const int* rowsA = eA; const int* colsA = eA + Ea;
    const int* rowsB = eB; const int* colsB = eB + Eb;

    void* p;
    cudaGetSymbolAddress(&p, g_H);    float* H    = (float*)p;
    cudaGetSymbolAddress(&p, g_AGGH); __half2* AGGH = (__half2*)p;
    cudaGetSymbolAddress(&p, g_H1);   float* H1E  = (float*)p;
    cudaGetSymbolAddress(&p, g_YA);   __half2* YA = (__half2*)p;
    cudaGetSymbolAddress(&p, g_YB);   __half2* YB = (__half2*)p;
    cudaGetSymbolAddress(&p, g_IN);   __half2* IN = (__half2*)p;
    cudaGetSymbolAddress(&p, g_disA); float* disA = (float*)p;
    cudaGetSymbolAddress(&p, g_disB); float* disB = (float*)p;
    cudaGetSymbolAddress(&p, g_invA); float* invA = (float*)p;
    cudaGetSymbolAddress(&p, g_invB); float* invB = (float*)p;
    cudaGetSymbolAddress(&p, g_icsr); int* icsr   = (int*)p;
    cudaGetSymbolAddress(&p, g_offs); int* offs   = (int*)p;
    cudaGetSymbolAddress(&p, g_src);  int* src    = (int*)p;
    cudaGetSymbolAddress(&p, g_bsums);int* bsums  = (int*)p;
    cudaGetSymbolAddress(&p, g_W16);  __half* W16 = (__half*)p;

    int* rowcntA = icsr;
    int* rowcntB = icsr + NMAX;
    int* colcnt  = icsr + 2 * NMAX;
    int* cursor  = icsr + 4 * NMAX;

    const size_t hstride = (size_t)NMAX * EMB;
    float* dout = (float*)d_out;

    cudaFuncSetAttribute(gemm_tc_kernel,
                         cudaFuncAttributeMaxDynamicSharedMemorySize, SMEM_TC);

    // ---- side stream for the CSR build (overlaps with encoder GEMMs) ----
    static cudaStream_t s2 = nullptr;
    static cudaEvent_t ev_fork = nullptr, ev_join = nullptr;
    if (!s2) {
        cudaStreamCreateWithFlags(&s2, cudaStreamNonBlocking);
        cudaEventCreateWithFlags(&ev_fork, cudaEventDisableTiming);
        cudaEventCreateWithFlags(&ev_join, cudaEventDisableTiming);
    }

    cudaEventRecord(ev_fork, 0);
    cudaStreamWaitEvent(s2, ev_fork, 0);

    // ---- CSR build + degrees (side stream) ----
    zero_kernel<<<(6 * NMAX + 255) / 256, 256, 0, s2>>>(icsr, 6 * NMAX);
    hist2_kernel<<<(Ea + 255) / 256, 256, 0, s2>>>(rowsA, colsA, rowcntA, colcnt, Ea);
    hist2_kernel<<<(Eb + 255) / 256, 256, 0, s2>>>(rowsB, colsB, rowcntB,
                                                   colcnt + NMAX, Eb);
    deg_fin_kernel<<<(N + 255) / 256, 256, 0, s2>>>(rowcntA, disA, invA, N);
    deg_fin_kernel<<<(N + 255) / 256, 256, 0, s2>>>(rowcntB, disB, invB, N);
    {
        const int n2 = 2 * NMAX;
        const int nb = (n2 + 1023) / 1024;
        scan_block_kernel<<<nb, 256, 0, s2>>>(colcnt, offs, bsums, n2);
        scan_sums_kernel<<<1, 512, 0, s2>>>(bsums, nb);
        scan_add_kernel<<<(n2 + 255) / 256, 256, 0, s2>>>(offs, bsums, n2);
    }
    fill_kernel<<<(Ea + 255) / 256, 256, 0, s2>>>(rowsA, colsA, offs, cursor, src,
                                                  Ea, 0);
    fill_kernel<<<(Eb + 255) / 256, 256, 0, s2>>>(rowsB, colsB, offs, cursor, src,
                                                  Eb, NMAX);
    cudaEventRecord(ev_join, s2);

    // ---- weight prep + encoder (main stream, concurrent with CSR build) ----
    prep_all_kernel<<<18 * 32, 256>>>(enc_w1, enc_w2, conv_w, reconv_w, W16);

    const int tiles = (N + 127) / 128;

    // enc1: single launch covering both N-halves (A tile staged once)
    gemm_tc_kernel<<<tiles, 256, SMEM_TC>>>(x, 32, N, 0,
        W16 + 0 * 8192, 1, 32, enc_b1, H1E, 256, 0, 1,
        nullptr, 0, 0, 0, nullptr, nullptr, nullptr, nullptr, nullptr,
        W16 + 1 * 8192, enc_b1 + 128, 128);
    // enc2 -> H0 + JK slice 0 of d_out
    gemm_tc_kernel<<<tiles, 256, SMEM_TC>>>(H1E, 256, N, 0,
        W16 + 2 * 8192, 4, 256, enc_b2, H, 128, 0, 1,
        dout, 0, rows_out, 0, nullptr, nullptr, nullptr, nullptr, nullptr,
        nullptr, nullptr, 0);

    // join: GCN layers need the CSR
    cudaStreamWaitEvent(0, ev_join, 0);

    // ---- GCN layers ----
    for (int l = 0; l < 3; l++) {
        const float* hl = H + (size_t)l * hstride;
        float* hn = H + (size_t)(l + 1) * hstride;
        const int last = (l == 2);

        // conv (edge set A): GEMM (fp32 A) -> IN (half init) + YA
        gemm_tc_kernel<<<tiles, 256, SMEM_TC>>>(hl, 128, N, 0,
            W16 + (6 + 2 * l) * 8192, 2, 128,
            conv_b + l * EMB, nullptr, 0, 0, 0,
            nullptr, 0, 0, 1, conv_rt + l * EMB, disA, invA, YA, IN,
            nullptr, nullptr, 0);
        agg_kernel<<<(N + 7) / 8, 256>>>(IN, YA, offs, colcnt, src, disA, AGGH, N, 0);

        // reconv (edge set B): GEMM reads fp16 AGGH directly -> IN + YB
        gemm_tc_kernel<<<tiles, 256, SMEM_TC>>>((const float*)AGGH, 0, N, 1,
            W16 + (12 + 2 * l) * 8192, 2, 128,
            reconv_b + l * EMB, nullptr, 0, 0, 0,
            nullptr, 0, 0, 1, reconv_rt + l * EMB, disB, invB, YB, IN,
            nullptr, nullptr, 0);

        if (!last) {
            agg_ln_kernel<<<(N + 7) / 8, 256>>>(IN, YB, offs, colcnt, src, disB,
                ln_g + l * EMB, ln_b + l * EMB, hl,
                hn, 128, 0, dout, (l + 1) * 128, rows_out, N, NMAX);
        } else {
            agg_ln_kernel<<<(rows_out + 7) / 8, 256>>>(IN, YB, offs, colcnt, src, disB,
                ln_g + l * EMB, ln_b + l * EMB, hl,
                dout, 512, 384, nullptr, 0, 0, rows_out, NMAX);
        }
    }
}